// round 14
// baseline (speedup 1.0000x reference)
#include <cuda_runtime.h>
#include <cuda_bf16.h>
#include <cstdint>

#define N_NODES 60000
#define N_HERB  5000
#define NOUT2   25000
#define DIM     128
#define NREL    6
#define NB      30
#define NE      600000
#define NP      40000
#define NSEG1   (N_NODES * NREL)   // 360000
#define NSEG2   (NOUT2 * NREL)     // 150000
#define SCAN_BLK 1024
#define NBLK    ((NSEG1 + SCAN_BLK - 1) / SCAN_BLK)   // 352

// phase-split points (row-aligned to 128-row GEMM blocks)
#define G1_BLKA 235
#define R1SPLIT (G1_BLKA * 128)        // 30080
#define G1_BLKB 234
#define S1A     (R1SPLIT * NREL)       // 180480
#define G2_BLKA 98
#define R2SPLIT (G2_BLKA * 128)        // 12544
#define G2_BLKB 98
#define S2A     (R2SPLIT * NREL)       // 75264

// ---------------- scratch ----------------
__device__ uint32_t g_A1h[(size_t)NSEG1 * 64], g_A1l[(size_t)NSEG1 * 64];
__device__ uint32_t g_A2h[(size_t)NSEG2 * 64], g_A2l[(size_t)NSEG2 * 64];
__device__ uint32_t g_Eh[(size_t)N_NODES * 64], g_El[(size_t)N_NODES * 64];
__device__ uint32_t g_X1h[(size_t)N_NODES * 64], g_X1l[(size_t)N_NODES * 64];  // full: layer-2 ptr targets
__device__ float g_x1[(size_t)N_NODES * DIM];
__device__ float g_x2[(size_t)NOUT2 * DIM];
__device__ int   g_cnt[NSEG1];
__device__ int   g_off[NSEG1 + 1];
__device__ int   g_cursor[NSEG1];
__device__ int   g_esrc[NE];
__device__ int   g_bsum[NBLK];
__device__ uint32_t g_BT1h[128 * 448], g_BT1l[128 * 448];
__device__ uint32_t g_BT2h[128 * 448], g_BT2l[128 * 448];
__device__ uint32_t g_SW1h[128 * 256], g_SW1l[128 * 256];
// segment indirection: per-seg pointers into A-rows / emb rows / zero page
__device__ unsigned long long g_p1h[NSEG1], g_p1l[NSEG1];
__device__ unsigned long long g_p2h[NSEG2], g_p2l[NSEG2];
__device__ uint32_t g_zero[64] = {};   // 256B zero page (never written)

// ---------------- helpers ----------------
__device__ __forceinline__ uint32_t smem_u32(const void* p) {
    uint32_t a;
    asm("{ .reg .u64 t; cvta.to.shared.u64 t, %1; cvt.u32.u64 %0, t; }" : "=r"(a) : "l"(p));
    return a;
}
__device__ __forceinline__ void ldm4(uint32_t* r, uint32_t addr) {
    asm volatile("ldmatrix.sync.aligned.m8n8.x4.shared.b16 {%0,%1,%2,%3}, [%4];"
        : "=r"(r[0]), "=r"(r[1]), "=r"(r[2]), "=r"(r[3]) : "r"(addr));
}
__device__ __forceinline__ void mma_bf16(float* d, const uint32_t* a, uint32_t b0, uint32_t b1) {
    asm volatile("mma.sync.aligned.m16n8k16.row.col.f32.bf16.bf16.f32 "
        "{%0,%1,%2,%3}, {%4,%5,%6,%7}, {%8,%9}, {%0,%1,%2,%3};"
        : "+f"(d[0]), "+f"(d[1]), "+f"(d[2]), "+f"(d[3])
        : "r"(a[0]), "r"(a[1]), "r"(a[2]), "r"(a[3]), "r"(b0), "r"(b1));
}
__device__ __forceinline__ uint32_t split_pack_hi(float2 f) {
    __nv_bfloat162 h;
    h.x = __float2bfloat16_rn(f.x); h.y = __float2bfloat16_rn(f.y);
    return *(uint32_t*)&h;
}
__device__ __forceinline__ uint32_t split_pack_lo(float2 f) {
    __nv_bfloat16 hx = __float2bfloat16_rn(f.x), hy = __float2bfloat16_rn(f.y);
    __nv_bfloat162 l;
    l.x = __float2bfloat16_rn(f.x - __bfloat162float(hx));
    l.y = __float2bfloat16_rn(f.y - __bfloat162float(hy));
    return *(uint32_t*)&l;
}
__device__ __forceinline__ void cpa16(uint32_t saddr, const void* g) {
    asm volatile("cp.async.cg.shared.global [%0], [%1], 16;" :: "r"(saddr), "l"(g));
}
#define CP_COMMIT() asm volatile("cp.async.commit_group;" ::: "memory")
#define CP_WAIT(n)  asm volatile("cp.async.wait_group %0;" :: "n"(n) : "memory")

#define PSTR 20
#define PTILE (128 * PSTR * 4)    // 10240 B
#define PSMEM (8 * PTILE)         // 81920 B -> 2 CTAs/SM
#define SSTR 36
#define STILE (128 * SSTR * 4)    // 18432 B
#define SSMEM (4 * STILE)         // 73728 B -> 2 CTAs/SM

// ---------------- merged weight/emb build ----------------
#define BLD_W1   (128 * 448)
#define BLD_W2   (BLD_W1 + 128 * 448)
#define BLD_SW   (BLD_W2 + 128 * 256)
#define BLD_EMB  (BLD_SW + N_NODES * 32)
__global__ void k_build_all(const float* __restrict__ basis1, const float* __restrict__ comp1,
                            const float* __restrict__ root1,
                            const float* __restrict__ basis2, const float* __restrict__ comp2,
                            const float* __restrict__ root2,
                            const float* __restrict__ sw1, const float* __restrict__ X) {
    int gid = blockIdx.x * blockDim.x + threadIdx.x;
    if (gid >= BLD_EMB) return;
    if (gid < BLD_W2) {
        const float* basis = (gid < BLD_W1) ? basis1 : basis2;
        const float* comp  = (gid < BLD_W1) ? comp1 : comp2;
        const float* root  = (gid < BLD_W1) ? root1 : root2;
        uint32_t* dh = (gid < BLD_W1) ? g_BT1h : g_BT2h;
        uint32_t* dl = (gid < BLD_W1) ? g_BT1l : g_BT2l;
        int idx = (gid < BLD_W1) ? gid : gid - BLD_W1;
        int o = idx / 448, j = idx % 448, k0 = j * 2;
        float w0, w1;
        if (k0 < 768) {
            int r = k0 >> 7, d0 = k0 & 127;
            w0 = 0.f; w1 = 0.f;
            #pragma unroll
            for (int b = 0; b < NB; b++) {
                float cc = comp[r * NB + b];
                w0 += cc * basis[b * 16384 + d0 * 128 + o];
                w1 += cc * basis[b * 16384 + (d0 + 1) * 128 + o];
            }
        } else {
            int d0 = k0 - 768;
            w0 = root[d0 * 128 + o]; w1 = root[(d0 + 1) * 128 + o];
        }
        float2 f = make_float2(w0, w1);
        dh[idx] = split_pack_hi(f);
        dl[idx] = split_pack_lo(f);
    } else if (gid < BLD_SW) {
        int idx = gid - BLD_W2;
        int o = idx >> 8, j = idx & 255, k0 = j * 2;
        float2 f = make_float2(sw1[k0 * 128 + o], sw1[(k0 + 1) * 128 + o]);
        g_SW1h[idx] = split_pack_hi(f);
        g_SW1l[idx] = split_pack_lo(f);
    } else {
        int idx = gid - BLD_SW;
        float4 f = ((const float4*)X)[idx];
        float2 f01 = make_float2(f.x, f.y), f23 = make_float2(f.z, f.w);
        *(uint2*)(g_Eh + (size_t)idx * 2) = make_uint2(split_pack_hi(f01), split_pack_hi(f23));
        *(uint2*)(g_El + (size_t)idx * 2) = make_uint2(split_pack_lo(f01), split_pack_lo(f23));
    }
}

// ---------------- CSR build ----------------
__global__ void k_count(const int* __restrict__ ei, const int* __restrict__ et) {
    int e = blockIdx.x * blockDim.x + threadIdx.x;
    if (e < NE) atomicAdd(&g_cnt[ei[NE + e] * NREL + et[e]], 1);
}
__global__ __launch_bounds__(SCAN_BLK) void k_scan_a() {
    __shared__ int sm[SCAN_BLK];
    int t = threadIdx.x;
    int gid = blockIdx.x * SCAN_BLK + t;
    int v = (gid < NSEG1) ? g_cnt[gid] : 0;
    sm[t] = v;
    __syncthreads();
    for (int d = 1; d < SCAN_BLK; d <<= 1) {
        int x = (t >= d) ? sm[t - d] : 0;
        __syncthreads();
        sm[t] += x;
        __syncthreads();
    }
    if (gid < NSEG1) g_off[gid] = sm[t] - v;
    if (t == SCAN_BLK - 1) g_bsum[blockIdx.x] = sm[t];
}
__global__ __launch_bounds__(SCAN_BLK) void k_scan_c() {
    __shared__ int red[SCAN_BLK];
    int t = threadIdx.x;
    red[t] = (t < (int)blockIdx.x && t < NBLK) ? g_bsum[t] : 0;
    __syncthreads();
    for (int d = SCAN_BLK / 2; d > 0; d >>= 1) {
        if (t < d) red[t] += red[t + d];
        __syncthreads();
    }
    int pre = red[0];
    int gid = blockIdx.x * SCAN_BLK + t;
    if (gid < NSEG1) {
        int o = g_off[gid] + pre;
        g_off[gid] = o;
        g_cursor[gid] = o;
    }
    if (gid == 0) g_off[NSEG1] = NE;
}
__global__ void k_fill(const int* __restrict__ ei, const int* __restrict__ et) {
    int e = blockIdx.x * blockDim.x + threadIdx.x;
    if (e < NE) {
        int seg = ei[NE + e] * NREL + et[e];
        int pos = atomicAdd(&g_cursor[seg], 1);
        g_esrc[pos] = ei[e];
    }
}

// ---------------- gathers: means for cnt>=2; pointer-indirection for cnt<=1 ----------------
__global__ __launch_bounds__(256) void k_gather1(const float* __restrict__ X, int seg0, int nseg) {
    int w = (int)((blockIdx.x * 256u + threadIdx.x) >> 5);
    if (w >= nseg) return;
    w += seg0;
    int lane = threadIdx.x & 31;
    int s0 = g_off[w], s1 = g_off[w + 1];
    int cnt = s1 - s0;
    if (cnt == 0) {
        if (lane == 0) {
            g_p1h[w] = (unsigned long long)(size_t)g_zero;
            g_p1l[w] = (unsigned long long)(size_t)g_zero;
        }
        return;
    }
    if (cnt == 1) {
        if (lane == 0) {
            int src = g_esrc[s0];
            g_p1h[w] = (unsigned long long)(size_t)(g_Eh + (size_t)src * 64);
            g_p1l[w] = (unsigned long long)(size_t)(g_El + (size_t)src * 64);
        }
        return;
    }
    float4 acc = make_float4(0.f, 0.f, 0.f, 0.f);
    for (int e = s0; e < s1; e++) {
        const float4 v = *(const float4*)(X + (size_t)g_esrc[e] * DIM + lane * 4);
        acc.x += v.x; acc.y += v.y; acc.z += v.z; acc.w += v.w;
    }
    float sc = 1.f / (float)cnt;
    float2 f01 = make_float2(acc.x * sc, acc.y * sc);
    float2 f23 = make_float2(acc.z * sc, acc.w * sc);
    size_t base = (size_t)w * 64 + lane * 2;
    *(uint2*)(g_A1h + base) = make_uint2(split_pack_hi(f01), split_pack_hi(f23));
    *(uint2*)(g_A1l + base) = make_uint2(split_pack_lo(f01), split_pack_lo(f23));
    if (lane == 0) {
        g_p1h[w] = (unsigned long long)(size_t)(g_A1h + (size_t)w * 64);
        g_p1l[w] = (unsigned long long)(size_t)(g_A1l + (size_t)w * 64);
    }
}
__global__ __launch_bounds__(256) void k_gather2(int seg0, int nseg) {
    int w = (int)((blockIdx.x * 256u + threadIdx.x) >> 5);
    if (w >= nseg) return;
    w += seg0;
    int lane = threadIdx.x & 31;
    int s0 = g_off[w], s1 = g_off[w + 1];
    int cnt = s1 - s0;
    if (cnt == 0) {
        if (lane == 0) {
            g_p2h[w] = (unsigned long long)(size_t)g_zero;
            g_p2l[w] = (unsigned long long)(size_t)g_zero;
        }
        return;
    }
    if (cnt == 1) {
        if (lane == 0) {
            int src = g_esrc[s0];
            g_p2h[w] = (unsigned long long)(size_t)(g_X1h + (size_t)src * 64);
            g_p2l[w] = (unsigned long long)(size_t)(g_X1l + (size_t)src * 64);
        }
        return;
    }
    float4 acc = make_float4(0.f, 0.f, 0.f, 0.f);
    for (int e = s0; e < s1; e++) {
        const float4 v = *(const float4*)(g_x1 + (size_t)g_esrc[e] * DIM + lane * 4);
        acc.x += v.x; acc.y += v.y; acc.z += v.z; acc.w += v.w;
    }
    float sc = 1.f / (float)cnt;
    float2 f01 = make_float2(acc.x * sc, acc.y * sc);
    float2 f23 = make_float2(acc.z * sc, acc.w * sc);
    size_t base = (size_t)w * 64 + lane * 2;
    *(uint2*)(g_A2h + base) = make_uint2(split_pack_hi(f01), split_pack_hi(f23));
    *(uint2*)(g_A2l + base) = make_uint2(split_pack_lo(f01), split_pack_lo(f23));
    if (lane == 0) {
        g_p2h[w] = (unsigned long long)(size_t)(g_A2h + (size_t)w * 64);
        g_p2l[w] = (unsigned long long)(size_t)(g_A2l + (size_t)w * 64);
    }
}

// ---------------- pipelined HMMA GEMM core (pointer-indirect A) ----------------
#define STAGE_CHUNK(c_, s_, PTRH, PTRL, ROOTH, ROOTL, BTH, BTL, NLIM)                         \
    do {                                                                                      \
        int cc = (c_);                                                                        \
        uint32_t sb0 = sbase + (uint32_t)((s_) * 4) * PTILE;                                  \
        _Pragma("unroll")                                                                     \
        for (int k = 0; k < 2; k++) {                                                         \
            int idx = tid + k * 256;                                                          \
            int row = idx >> 2, c16 = idx & 3;                                                \
            int grow = m0 + row; if (grow >= (NLIM)) grow = (NLIM) - 1;                       \
            const uint32_t *srch, *srcl;                                                      \
            if (cc < 24) {                                                                    \
                int seg = grow * 6 + (cc >> 2);                                               \
                srch = (const uint32_t*)(size_t)(PTRH)[seg] + (cc & 3) * 16;                  \
                srcl = (const uint32_t*)(size_t)(PTRL)[seg] + (cc & 3) * 16;                  \
            } else {                                                                          \
                size_t sgb = (size_t)grow * 64 + (cc - 24) * 16;                              \
                srch = (ROOTH) + sgb; srcl = (ROOTL) + sgb;                                   \
            }                                                                                 \
            uint32_t so = (uint32_t)(row * 80 + c16 * 16);                                    \
            cpa16(sb0 + 0 * PTILE + so, srch + c16 * 4);                                      \
            cpa16(sb0 + 1 * PTILE + so, srcl + c16 * 4);                                      \
            const uint32_t* bh = (BTH) + (size_t)row * 448 + cc * 16;                         \
            const uint32_t* bl = (BTL) + (size_t)row * 448 + cc * 16;                         \
            cpa16(sb0 + 2 * PTILE + so, bh + c16 * 4);                                        \
            cpa16(sb0 + 3 * PTILE + so, bl + c16 * 4);                                        \
        }                                                                                     \
        CP_COMMIT();                                                                          \
    } while (0)

#define MMA_CHUNK(s_)                                                                         \
    do {                                                                                      \
        uint32_t sb0 = sbase + (uint32_t)((s_) * 4) * PTILE;                                  \
        _Pragma("unroll")                                                                     \
        for (int kk = 0; kk < 2; kk++) {                                                      \
            uint32_t ah[2][4], al[2][4], bh[4][4], bl[4][4];                                  \
            _Pragma("unroll")                                                                 \
            for (int mt = 0; mt < 2; mt++) {                                                  \
                uint32_t off = (uint32_t)((wm * 32 + mt * 16 + lrow) * 80 + kk * 32 + lk * 16); \
                ldm4(ah[mt], sb0 + 0 * PTILE + off);                                          \
                ldm4(al[mt], sb0 + 1 * PTILE + off);                                          \
            }                                                                                 \
            _Pragma("unroll")                                                                 \
            for (int nt = 0; nt < 4; nt++) {                                                  \
                uint32_t off = (uint32_t)((wn * 64 + nt * 16 + lrow) * 80 + kk * 32 + lk * 16); \
                ldm4(bh[nt], sb0 + 2 * PTILE + off);                                          \
                ldm4(bl[nt], sb0 + 3 * PTILE + off);                                          \
            }                                                                                 \
            _Pragma("unroll")                                                                 \
            for (int mt = 0; mt < 2; mt++)                                                    \
                _Pragma("unroll")                                                             \
                for (int nt = 0; nt < 4; nt++) {                                              \
                    mma_bf16(acc[mt][2 * nt],     ah[mt], bh[nt][0], bh[nt][2]);              \
                    mma_bf16(acc[mt][2 * nt + 1], ah[mt], bh[nt][1], bh[nt][3]);              \
                    mma_bf16(acc[mt][2 * nt],     al[mt], bh[nt][0], bh[nt][2]);              \
                    mma_bf16(acc[mt][2 * nt + 1], al[mt], bh[nt][1], bh[nt][3]);              \
                    mma_bf16(acc[mt][2 * nt],     ah[mt], bl[nt][0], bl[nt][2]);              \
                    mma_bf16(acc[mt][2 * nt + 1], ah[mt], bl[nt][1], bl[nt][3]);              \
                }                                                                             \
        }                                                                                     \
    } while (0)

// GEMM1: x1 = relu([agg1 | emb] @ B1' + bias1); split X1 written for ALL rows
__global__ __launch_bounds__(256, 2) void k_gemm1_p(const float* __restrict__ bias1, int row_base) {
    extern __shared__ char sm[];
    const uint32_t sbase = smem_u32(sm);
    const int tid = threadIdx.x, lane = tid & 31, wid = tid >> 5;
    const int wm = wid & 3, wn = wid >> 2;
    const int lrow = lane & 15, lk = lane >> 4;
    const int m0 = row_base + blockIdx.x * 128;

    float acc[2][8][4];
    #pragma unroll
    for (int i = 0; i < 2; i++)
        #pragma unroll
        for (int j = 0; j < 8; j++)
            #pragma unroll
            for (int c = 0; c < 4; c++) acc[i][j][c] = 0.f;

    STAGE_CHUNK(0, 0, g_p1h, g_p1l, g_Eh, g_El, g_BT1h, g_BT1l, N_NODES);
    for (int c = 0; c < 28; c++) {
        int s = c & 1;
        if (c < 27) {
            STAGE_CHUNK(c + 1, s ^ 1, g_p1h, g_p1l, g_Eh, g_El, g_BT1h, g_BT1l, N_NODES);
            CP_WAIT(1);
        } else {
            CP_WAIT(0);
        }
        __syncthreads();
        MMA_CHUNK(s);
        __syncthreads();
    }

    const int g = lane >> 2, tc = lane & 3;
    #pragma unroll
    for (int mt = 0; mt < 2; mt++) {
        #pragma unroll
        for (int nb = 0; nb < 8; nb++) {
            int col = wn * 64 + nb * 8 + tc * 2;
            float b0 = bias1[col], b1 = bias1[col + 1];
            int pi = col >> 1;
            int r0 = m0 + wm * 32 + mt * 16 + g;
            if (r0 < N_NODES) {
                float2 v = make_float2(fmaxf(acc[mt][nb][0] + b0, 0.f), fmaxf(acc[mt][nb][1] + b1, 0.f));
                *(float2*)(g_x1 + (size_t)r0 * DIM + col) = v;
                g_X1h[(size_t)r0 * 64 + pi] = split_pack_hi(v);
                g_X1l[(size_t)r0 * 64 + pi] = split_pack_lo(v);
            }
            int r1 = r0 + 8;
            if (r1 < N_NODES) {
                float2 v = make_float2(fmaxf(acc[mt][nb][2] + b0, 0.f), fmaxf(acc[mt][nb][3] + b1, 0.f));
                *(float2*)(g_x1 + (size_t)r1 * DIM + col) = v;
                g_X1h[(size_t)r1 * 64 + pi] = split_pack_hi(v);
                g_X1l[(size_t)r1 * 64 + pi] = split_pack_lo(v);
            }
        }
    }
}

// GEMM2: x2 = [agg2 | x1] @ B2' + bias2
__global__ __launch_bounds__(256, 2) void k_gemm2_p(const float* __restrict__ bias2, int row_base) {
    extern __shared__ char sm[];
    const uint32_t sbase = smem_u32(sm);
    const int tid = threadIdx.x, lane = tid & 31, wid = tid >> 5;
    const int wm = wid & 3, wn = wid >> 2;
    const int lrow = lane & 15, lk = lane >> 4;
    const int m0 = row_base + blockIdx.x * 128;

    float acc[2][8][4];
    #pragma unroll
    for (int i = 0; i < 2; i++)
        #pragma unroll
        for (int j = 0; j < 8; j++)
            #pragma unroll
            for (int c = 0; c < 4; c++) acc[i][j][c] = 0.f;

    STAGE_CHUNK(0, 0, g_p2h, g_p2l, g_X1h, g_X1l, g_BT2h, g_BT2l, NOUT2);
    for (int c = 0; c < 28; c++) {
        int s = c & 1;
        if (c < 27) {
            STAGE_CHUNK(c + 1, s ^ 1, g_p2h, g_p2l, g_X1h, g_X1l, g_BT2h, g_BT2l, NOUT2);
            CP_WAIT(1);
        } else {
            CP_WAIT(0);
        }
        __syncthreads();
        MMA_CHUNK(s);
        __syncthreads();
    }

    const int g = lane >> 2, tc = lane & 3;
    #pragma unroll
    for (int mt = 0; mt < 2; mt++) {
        #pragma unroll
        for (int nb = 0; nb < 8; nb++) {
            int col = wn * 64 + nb * 8 + tc * 2;
            float b0 = bias2[col], b1 = bias2[col + 1];
            int r0 = m0 + wm * 32 + mt * 16 + g;
            if (r0 < NOUT2)
                *(float2*)(g_x2 + (size_t)r0 * DIM + col) =
                    make_float2(acc[mt][nb][0] + b0, acc[mt][nb][1] + b1);
            int r1 = r0 + 8;
            if (r1 < NOUT2)
                *(float2*)(g_x2 + (size_t)r1 * DIM + col) =
                    make_float2(acc[mt][nb][2] + b0, acc[mt][nb][3] + b1);
        }
    }
}

// ---------------- scorer (HMMA): K=64 chunks, 2 CTAs/SM ----------------
__global__ __launch_bounds__(256, 2) void k_scorer_mma(const int* __restrict__ h_idx, const int* __restrict__ p_idx,
                                                       const float* __restrict__ sb1, const float* __restrict__ sw2,
                                                       const float* __restrict__ sb2, float* __restrict__ out) {
    extern __shared__ char sm[];
    __shared__ int sh_h[128], sh_p[128];
    uint32_t* Ah = (uint32_t*)sm;
    uint32_t* Al = (uint32_t*)(sm + STILE);
    const uint32_t sAh = smem_u32(sm), sAl = sAh + STILE, sBh = sAh + 2 * STILE, sBl = sAh + 3 * STILE;
    const int tid = threadIdx.x, lane = tid & 31, wid = tid >> 5;
    const int wm = wid & 3, wn = wid >> 2;
    const int lrow = lane & 15, lk = lane >> 4;
    const int pair0 = blockIdx.x * 128;

    for (int i = tid; i < 128; i += 256) {
        int pr = pair0 + i; if (pr >= NP) pr = NP - 1;
        sh_h[i] = h_idx[pr];
        sh_p[i] = N_HERB + p_idx[pr];
    }
    __syncthreads();

    float acc[2][8][4];
    #pragma unroll
    for (int i = 0; i < 2; i++)
        #pragma unroll
        for (int j = 0; j < 8; j++)
            #pragma unroll
            for (int c = 0; c < 4; c++) acc[i][j][c] = 0.f;

    for (int c = 0; c < 8; c++) {
        for (int i = tid; i < 1024; i += 256) {
            int row = i >> 3, c16 = i & 7;
            uint32_t so = (uint32_t)(row * 144 + c16 * 16);
            cpa16(sBh + so, g_SW1h + (size_t)row * 256 + c * 32 + c16 * 4);
            cpa16(sBl + so, g_SW1l + (size_t)row * 256 + c * 32 + c16 * 4);
        }
        CP_COMMIT();
        for (int i = tid; i < 128 * 32; i += 256) {
            int row = i >> 5, k2 = i & 31;
            int pi = ((c & 1) << 5) + k2;
            const float2* hr = (const float2*)(g_x2 + (size_t)sh_h[row] * DIM);
            const float2* pr = (const float2*)(g_x2 + (size_t)sh_p[row] * DIM);
            float2 f;
            if (c < 2)      f = hr[pi];
            else if (c < 4) f = pr[pi];
            else if (c < 6) { float2 h = hr[pi], p = pr[pi]; f = make_float2(h.x * p.x, h.y * p.y); }
            else            { float2 h = hr[pi], p = pr[pi]; f = make_float2(fabsf(h.x - p.x), fabsf(h.y - p.y)); }
            Ah[row * SSTR + k2] = split_pack_hi(f);
            Al[row * SSTR + k2] = split_pack_lo(f);
        }
        CP_WAIT(0);
        __syncthreads();
        #pragma unroll
        for (int kk = 0; kk < 4; kk++) {
            uint32_t ah[2][4], al[2][4], bh[4][4], bl[4][4];
            #pragma unroll
            for (int mt = 0; mt < 2; mt++) {
                uint32_t off = (uint32_t)((wm * 32 + mt * 16 + lrow) * 144 + kk * 32 + lk * 16);
                ldm4(ah[mt], sAh + off);
                ldm4(al[mt], sAl + off);
            }
            #pragma unroll
            for (int nt = 0; nt < 4; nt++) {
                uint32_t off = (uint32_t)((wn * 64 + nt * 16 + lrow) * 144 + kk * 32 + lk * 16);
                ldm4(bh[nt], sBh + off);
                ldm4(bl[nt], sBl + off);
            }
            #pragma unroll
            for (int mt = 0; mt < 2; mt++)
                #pragma unroll
                for (int nt = 0; nt < 4; nt++) {
                    mma_bf16(acc[mt][2 * nt],     ah[mt], bh[nt][0], bh[nt][2]);
                    mma_bf16(acc[mt][2 * nt + 1], ah[mt], bh[nt][1], bh[nt][3]);
                    mma_bf16(acc[mt][2 * nt],     al[mt], bh[nt][0], bh[nt][2]);
                    mma_bf16(acc[mt][2 * nt + 1], al[mt], bh[nt][1], bh[nt][3]);
                    mma_bf16(acc[mt][2 * nt],     ah[mt], bl[nt][0], bl[nt][2]);
                    mma_bf16(acc[mt][2 * nt + 1], ah[mt], bl[nt][1], bl[nt][3]);
                }
        }
        __syncthreads();
    }

    __syncthreads();
    float* s_part = (float*)sm;
    const int g = lane >> 2, tc = lane & 3;
    #pragma unroll
    for (int mt = 0; mt < 2; mt++) {
        float s0 = 0.f, s1 = 0.f;
        #pragma unroll
        for (int nb = 0; nb < 8; nb++) {
            int col = wn * 64 + nb * 8 + tc * 2;
            float w0 = sw2[col], w1 = sw2[col + 1];
            float bb0 = sb1[col], bb1 = sb1[col + 1];
            s0 += fmaxf(acc[mt][nb][0] + bb0, 0.f) * w0 + fmaxf(acc[mt][nb][1] + bb1, 0.f) * w1;
            s1 += fmaxf(acc[mt][nb][2] + bb0, 0.f) * w0 + fmaxf(acc[mt][nb][3] + bb1, 0.f) * w1;
        }
        s0 += __shfl_xor_sync(0xffffffff, s0, 1); s0 += __shfl_xor_sync(0xffffffff, s0, 2);
        s1 += __shfl_xor_sync(0xffffffff, s1, 1); s1 += __shfl_xor_sync(0xffffffff, s1, 2);
        if (tc == 0) {
            int r0 = wm * 32 + mt * 16 + g;
            s_part[r0 * 2 + wn] = s0;
            s_part[(r0 + 8) * 2 + wn] = s1;
        }
    }
    __syncthreads();
    if (tid < 128) {
        int pr = pair0 + tid;
        if (pr < NP) out[pr] = s_part[tid * 2] + s_part[tid * 2 + 1] + sb2[0];
    }
}

// ---------------- launch ----------------
extern "C" void kernel_launch(void* const* d_in, const int* in_sizes, int n_in,
                              void* d_out, int out_size) {
    const int*   edge_index = (const int*)d_in[0];
    const int*   edge_type  = (const int*)d_in[1];
    const int*   h_idx      = (const int*)d_in[2];
    const int*   p_idx      = (const int*)d_in[3];
    const float* node_emb   = (const float*)d_in[4];
    const float* basis1 = (const float*)d_in[5];
    const float* comp1  = (const float*)d_in[6];
    const float* root1  = (const float*)d_in[7];
    const float* bias1  = (const float*)d_in[8];
    const float* basis2 = (const float*)d_in[9];
    const float* comp2  = (const float*)d_in[10];
    const float* root2  = (const float*)d_in[11];
    const float* bias2  = (const float*)d_in[12];
    const float* sw1 = (const float*)d_in[13];
    const float* sb1 = (const float*)d_in[14];
    const float* sw2 = (const float*)d_in[15];
    const float* sb2 = (const float*)d_in[16];
    float* out = (float*)d_out;

    cudaFuncSetAttribute(k_gemm1_p, cudaFuncAttributeMaxDynamicSharedMemorySize, PSMEM);
    cudaFuncSetAttribute(k_gemm2_p, cudaFuncAttributeMaxDynamicSharedMemorySize, PSMEM);
    cudaFuncSetAttribute(k_scorer_mma, cudaFuncAttributeMaxDynamicSharedMemorySize, SSMEM);

    static cudaStream_t s1 = nullptr;
    static cudaEvent_t evFork = nullptr, evG1A = nullptr, evM1A = nullptr,
                       evG2A = nullptr, evM2A = nullptr, evBuild = nullptr;
    if (s1 == nullptr) {
        cudaStreamCreateWithFlags(&s1, cudaStreamNonBlocking);
        cudaEventCreateWithFlags(&evFork, cudaEventDisableTiming);
        cudaEventCreateWithFlags(&evBuild, cudaEventDisableTiming);
        cudaEventCreateWithFlags(&evG1A, cudaEventDisableTiming);
        cudaEventCreateWithFlags(&evM1A, cudaEventDisableTiming);
        cudaEventCreateWithFlags(&evG2A, cudaEventDisableTiming);
        cudaEventCreateWithFlags(&evM2A, cudaEventDisableTiming);
    }

    // fork: builds on s1
    cudaEventRecord(evFork, 0);
    cudaStreamWaitEvent(s1, evFork, 0);
    k_build_all<<<(BLD_EMB + 255) / 256, 256, 0, s1>>>(basis1, comp1, root1,
                                                       basis2, comp2, root2,
                                                       sw1, node_emb);
    cudaEventRecord(evBuild, s1);

    // main: CSR
    int* cnt_ptr = nullptr;
    cudaGetSymbolAddress((void**)&cnt_ptr, g_cnt);
    cudaMemsetAsync(cnt_ptr, 0, NSEG1 * sizeof(int), 0);
    k_count<<<(NE + 255) / 256, 256>>>(edge_index, edge_type);
    k_scan_a<<<NBLK, SCAN_BLK>>>();
    k_scan_c<<<NBLK, SCAN_BLK>>>();
    k_fill<<<(NE + 255) / 256, 256>>>(edge_index, edge_type);

    // gather1a on main; gemm1a (s1) overlaps gather1b (main)
    k_gather1<<<(S1A * 32 + 255) / 256, 256>>>(node_emb, 0, S1A);
    cudaEventRecord(evG1A, 0);

    cudaStreamWaitEvent(s1, evG1A, 0);      // s1: build done (in-order) + g1a pointers/data ready
    k_gemm1_p<<<G1_BLKA, 256, PSMEM, s1>>>(bias1, 0);
    cudaEventRecord(evM1A, s1);

    k_gather1<<<((NSEG1 - S1A) * 32 + 255) / 256, 256>>>(node_emb, S1A, NSEG1 - S1A);
    cudaStreamWaitEvent(0, evBuild, 0);
    k_gemm1_p<<<G1_BLKB, 256, PSMEM>>>(bias1, R1SPLIT);
    cudaStreamWaitEvent(0, evM1A, 0);       // x1/X1 fully written

    // gather2a on main; gemm2a (s1) overlaps gather2b (main)
    k_gather2<<<(S2A * 32 + 255) / 256, 256>>>(0, S2A);
    cudaEventRecord(evG2A, 0);

    cudaStreamWaitEvent(s1, evG2A, 0);
    k_gemm2_p<<<G2_BLKA, 256, PSMEM, s1>>>(bias2, 0);
    cudaEventRecord(evM2A, s1);

    k_gather2<<<((NSEG2 - S2A) * 32 + 255) / 256, 256>>>(S2A, NSEG2 - S2A);
    k_gemm2_p<<<G2_BLKB, 256, PSMEM>>>(bias2, R2SPLIT);
    cudaStreamWaitEvent(0, evM2A, 0);       // x2 fully written

    k_scorer_mma<<<(NP + 127) / 128, 256, SSMEM>>>(h_idx, p_idx, sb1, sw2, sb2, out);
}

// round 15
// speedup vs baseline: 1.0081x; 1.0081x over previous
#include <cuda_runtime.h>
#include <cuda_bf16.h>
#include <cstdint>

#define N_NODES 60000
#define N_HERB  5000
#define NOUT2   25000
#define DIM     128
#define NREL    6
#define NB      30
#define NE      600000
#define NP      40000
#define NSEG1   (N_NODES * NREL)   // 360000
#define NSEG2   (NOUT2 * NREL)     // 150000
#define SCAN_BLK 1024
#define NBLK    ((NSEG1 + SCAN_BLK - 1) / SCAN_BLK)   // 352

// phase-split points (row-aligned to 128-row GEMM blocks)
#define G1_BLKA 235
#define R1SPLIT (G1_BLKA * 128)        // 30080
#define G1_BLKB 234
#define S1A     (R1SPLIT * NREL)       // 180480
#define G2_BLKA 98
#define R2SPLIT (G2_BLKA * 128)        // 12544
#define G2_BLKB 98
#define S2A     (R2SPLIT * NREL)       // 75264

// ---------------- scratch ----------------
__device__ uint32_t g_A1h[(size_t)NSEG1 * 64], g_A1l[(size_t)NSEG1 * 64];
__device__ uint32_t g_A2h[(size_t)NSEG2 * 64], g_A2l[(size_t)NSEG2 * 64];
__device__ uint32_t g_Eh[(size_t)N_NODES * 64], g_El[(size_t)N_NODES * 64];
__device__ uint32_t g_X1h[(size_t)N_NODES * 64], g_X1l[(size_t)N_NODES * 64];  // full: layer-2 ptr targets
__device__ float g_x1[(size_t)N_NODES * DIM];
__device__ float g_x2[(size_t)NOUT2 * DIM];
__device__ int   g_cnt[NSEG1];
__device__ int   g_off[NSEG1 + 1];
__device__ int   g_cursor[NSEG1];
__device__ int   g_esrc[NE];
__device__ int   g_bsum[NBLK];
__device__ uint32_t g_BT1h[128 * 448], g_BT1l[128 * 448];
__device__ uint32_t g_BT2h[128 * 448], g_BT2l[128 * 448];
__device__ uint32_t g_SW1h[128 * 256], g_SW1l[128 * 256];
// segment indirection: per-seg pointers into A-rows / emb rows / zero page
__device__ unsigned long long g_p1h[NSEG1], g_p1l[NSEG1];
__device__ unsigned long long g_p2h[NSEG2], g_p2l[NSEG2];
__device__ uint32_t g_zero[64] = {};   // 256B zero page (never written)

// ---------------- helpers ----------------
__device__ __forceinline__ uint32_t smem_u32(const void* p) {
    uint32_t a;
    asm("{ .reg .u64 t; cvta.to.shared.u64 t, %1; cvt.u32.u64 %0, t; }" : "=r"(a) : "l"(p));
    return a;
}
__device__ __forceinline__ void ldm4(uint32_t* r, uint32_t addr) {
    asm volatile("ldmatrix.sync.aligned.m8n8.x4.shared.b16 {%0,%1,%2,%3}, [%4];"
        : "=r"(r[0]), "=r"(r[1]), "=r"(r[2]), "=r"(r[3]) : "r"(addr));
}
__device__ __forceinline__ void mma_bf16(float* d, const uint32_t* a, uint32_t b0, uint32_t b1) {
    asm volatile("mma.sync.aligned.m16n8k16.row.col.f32.bf16.bf16.f32 "
        "{%0,%1,%2,%3}, {%4,%5,%6,%7}, {%8,%9}, {%0,%1,%2,%3};"
        : "+f"(d[0]), "+f"(d[1]), "+f"(d[2]), "+f"(d[3])
        : "r"(a[0]), "r"(a[1]), "r"(a[2]), "r"(a[3]), "r"(b0), "r"(b1));
}
__device__ __forceinline__ uint32_t split_pack_hi(float2 f) {
    __nv_bfloat162 h;
    h.x = __float2bfloat16_rn(f.x); h.y = __float2bfloat16_rn(f.y);
    return *(uint32_t*)&h;
}
__device__ __forceinline__ uint32_t split_pack_lo(float2 f) {
    __nv_bfloat16 hx = __float2bfloat16_rn(f.x), hy = __float2bfloat16_rn(f.y);
    __nv_bfloat162 l;
    l.x = __float2bfloat16_rn(f.x - __bfloat162float(hx));
    l.y = __float2bfloat16_rn(f.y - __bfloat162float(hy));
    return *(uint32_t*)&l;
}
__device__ __forceinline__ void cpa16(uint32_t saddr, const void* g) {
    asm volatile("cp.async.cg.shared.global [%0], [%1], 16;" :: "r"(saddr), "l"(g));
}
#define CP_COMMIT() asm volatile("cp.async.commit_group;" ::: "memory")
#define CP_WAIT(n)  asm volatile("cp.async.wait_group %0;" :: "n"(n) : "memory")

#define PSTR 20
#define PTILE (128 * PSTR * 4)    // 10240 B
#define PSMEM (8 * PTILE)         // 81920 B dynamic (+12KB static ptr cache) -> 2 CTAs/SM
#define SSTR 36
#define STILE (128 * SSTR * 4)    // 18432 B
#define SSMEM (4 * STILE)         // 73728 B -> 2 CTAs/SM

// ---------------- merged weight/emb build ----------------
#define BLD_W1   (128 * 448)
#define BLD_W2   (BLD_W1 + 128 * 448)
#define BLD_SW   (BLD_W2 + 128 * 256)
#define BLD_EMB  (BLD_SW + N_NODES * 32)
__global__ void k_build_all(const float* __restrict__ basis1, const float* __restrict__ comp1,
                            const float* __restrict__ root1,
                            const float* __restrict__ basis2, const float* __restrict__ comp2,
                            const float* __restrict__ root2,
                            const float* __restrict__ sw1, const float* __restrict__ X) {
    int gid = blockIdx.x * blockDim.x + threadIdx.x;
    if (gid >= BLD_EMB) return;
    if (gid < BLD_W2) {
        const float* basis = (gid < BLD_W1) ? basis1 : basis2;
        const float* comp  = (gid < BLD_W1) ? comp1 : comp2;
        const float* root  = (gid < BLD_W1) ? root1 : root2;
        uint32_t* dh = (gid < BLD_W1) ? g_BT1h : g_BT2h;
        uint32_t* dl = (gid < BLD_W1) ? g_BT1l : g_BT2l;
        int idx = (gid < BLD_W1) ? gid : gid - BLD_W1;
        int o = idx / 448, j = idx % 448, k0 = j * 2;
        float w0, w1;
        if (k0 < 768) {
            int r = k0 >> 7, d0 = k0 & 127;
            w0 = 0.f; w1 = 0.f;
            #pragma unroll
            for (int b = 0; b < NB; b++) {
                float cc = comp[r * NB + b];
                w0 += cc * basis[b * 16384 + d0 * 128 + o];
                w1 += cc * basis[b * 16384 + (d0 + 1) * 128 + o];
            }
        } else {
            int d0 = k0 - 768;
            w0 = root[d0 * 128 + o]; w1 = root[(d0 + 1) * 128 + o];
        }
        float2 f = make_float2(w0, w1);
        dh[idx] = split_pack_hi(f);
        dl[idx] = split_pack_lo(f);
    } else if (gid < BLD_SW) {
        int idx = gid - BLD_W2;
        int o = idx >> 8, j = idx & 255, k0 = j * 2;
        float2 f = make_float2(sw1[k0 * 128 + o], sw1[(k0 + 1) * 128 + o]);
        g_SW1h[idx] = split_pack_hi(f);
        g_SW1l[idx] = split_pack_lo(f);
    } else {
        int idx = gid - BLD_SW;
        float4 f = ((const float4*)X)[idx];
        float2 f01 = make_float2(f.x, f.y), f23 = make_float2(f.z, f.w);
        *(uint2*)(g_Eh + (size_t)idx * 2) = make_uint2(split_pack_hi(f01), split_pack_hi(f23));
        *(uint2*)(g_El + (size_t)idx * 2) = make_uint2(split_pack_lo(f01), split_pack_lo(f23));
    }
}

// ---------------- CSR build ----------------
__global__ void k_count(const int* __restrict__ ei, const int* __restrict__ et) {
    int e = blockIdx.x * blockDim.x + threadIdx.x;
    if (e < NE) atomicAdd(&g_cnt[ei[NE + e] * NREL + et[e]], 1);
}
__global__ __launch_bounds__(SCAN_BLK) void k_scan_a() {
    __shared__ int sm[SCAN_BLK];
    int t = threadIdx.x;
    int gid = blockIdx.x * SCAN_BLK + t;
    int v = (gid < NSEG1) ? g_cnt[gid] : 0;
    sm[t] = v;
    __syncthreads();
    for (int d = 1; d < SCAN_BLK; d <<= 1) {
        int x = (t >= d) ? sm[t - d] : 0;
        __syncthreads();
        sm[t] += x;
        __syncthreads();
    }
    if (gid < NSEG1) g_off[gid] = sm[t] - v;
    if (t == SCAN_BLK - 1) g_bsum[blockIdx.x] = sm[t];
}
__global__ __launch_bounds__(SCAN_BLK) void k_scan_c() {
    __shared__ int red[SCAN_BLK];
    int t = threadIdx.x;
    red[t] = (t < (int)blockIdx.x && t < NBLK) ? g_bsum[t] : 0;
    __syncthreads();
    for (int d = SCAN_BLK / 2; d > 0; d >>= 1) {
        if (t < d) red[t] += red[t + d];
        __syncthreads();
    }
    int pre = red[0];
    int gid = blockIdx.x * SCAN_BLK + t;
    if (gid < NSEG1) {
        int o = g_off[gid] + pre;
        g_off[gid] = o;
        g_cursor[gid] = o;
    }
    if (gid == 0) g_off[NSEG1] = NE;
}
__global__ void k_fill(const int* __restrict__ ei, const int* __restrict__ et) {
    int e = blockIdx.x * blockDim.x + threadIdx.x;
    if (e < NE) {
        int seg = ei[NE + e] * NREL + et[e];
        int pos = atomicAdd(&g_cursor[seg], 1);
        g_esrc[pos] = ei[e];
    }
}

// ---------------- gathers: means for cnt>=2; pointer-indirection for cnt<=1 ----------------
__global__ __launch_bounds__(256) void k_gather1(const float* __restrict__ X, int seg0, int nseg) {
    int w = (int)((blockIdx.x * 256u + threadIdx.x) >> 5);
    if (w >= nseg) return;
    w += seg0;
    int lane = threadIdx.x & 31;
    int s0 = g_off[w], s1 = g_off[w + 1];
    int cnt = s1 - s0;
    if (cnt == 0) {
        if (lane == 0) {
            g_p1h[w] = (unsigned long long)(size_t)g_zero;
            g_p1l[w] = (unsigned long long)(size_t)g_zero;
        }
        return;
    }
    if (cnt == 1) {
        if (lane == 0) {
            int src = g_esrc[s0];
            g_p1h[w] = (unsigned long long)(size_t)(g_Eh + (size_t)src * 64);
            g_p1l[w] = (unsigned long long)(size_t)(g_El + (size_t)src * 64);
        }
        return;
    }
    float4 acc = make_float4(0.f, 0.f, 0.f, 0.f);
    for (int e = s0; e < s1; e++) {
        const float4 v = *(const float4*)(X + (size_t)g_esrc[e] * DIM + lane * 4);
        acc.x += v.x; acc.y += v.y; acc.z += v.z; acc.w += v.w;
    }
    float sc = 1.f / (float)cnt;
    float2 f01 = make_float2(acc.x * sc, acc.y * sc);
    float2 f23 = make_float2(acc.z * sc, acc.w * sc);
    size_t base = (size_t)w * 64 + lane * 2;
    *(uint2*)(g_A1h + base) = make_uint2(split_pack_hi(f01), split_pack_hi(f23));
    *(uint2*)(g_A1l + base) = make_uint2(split_pack_lo(f01), split_pack_lo(f23));
    if (lane == 0) {
        g_p1h[w] = (unsigned long long)(size_t)(g_A1h + (size_t)w * 64);
        g_p1l[w] = (unsigned long long)(size_t)(g_A1l + (size_t)w * 64);
    }
}
__global__ __launch_bounds__(256) void k_gather2(int seg0, int nseg) {
    int w = (int)((blockIdx.x * 256u + threadIdx.x) >> 5);
    if (w >= nseg) return;
    w += seg0;
    int lane = threadIdx.x & 31;
    int s0 = g_off[w], s1 = g_off[w + 1];
    int cnt = s1 - s0;
    if (cnt == 0) {
        if (lane == 0) {
            g_p2h[w] = (unsigned long long)(size_t)g_zero;
            g_p2l[w] = (unsigned long long)(size_t)g_zero;
        }
        return;
    }
    if (cnt == 1) {
        if (lane == 0) {
            int src = g_esrc[s0];
            g_p2h[w] = (unsigned long long)(size_t)(g_X1h + (size_t)src * 64);
            g_p2l[w] = (unsigned long long)(size_t)(g_X1l + (size_t)src * 64);
        }
        return;
    }
    float4 acc = make_float4(0.f, 0.f, 0.f, 0.f);
    for (int e = s0; e < s1; e++) {
        const float4 v = *(const float4*)(g_x1 + (size_t)g_esrc[e] * DIM + lane * 4);
        acc.x += v.x; acc.y += v.y; acc.z += v.z; acc.w += v.w;
    }
    float sc = 1.f / (float)cnt;
    float2 f01 = make_float2(acc.x * sc, acc.y * sc);
    float2 f23 = make_float2(acc.z * sc, acc.w * sc);
    size_t base = (size_t)w * 64 + lane * 2;
    *(uint2*)(g_A2h + base) = make_uint2(split_pack_hi(f01), split_pack_hi(f23));
    *(uint2*)(g_A2l + base) = make_uint2(split_pack_lo(f01), split_pack_lo(f23));
    if (lane == 0) {
        g_p2h[w] = (unsigned long long)(size_t)(g_A2h + (size_t)w * 64);
        g_p2l[w] = (unsigned long long)(size_t)(g_A2l + (size_t)w * 64);
    }
}

// ---------------- pipelined HMMA GEMM core (smem-cached pointer-indirect A) ----------------
// pointers preloaded once into s_ph/s_pl[row*6+r]; staging reads them via LDS (no global dep)
#define STAGE_CHUNK(c_, s_, ROOTH, ROOTL, BTH, BTL, NLIM)                                     \
    do {                                                                                      \
        int cc = (c_);                                                                        \
        uint32_t sb0 = sbase + (uint32_t)((s_) * 4) * PTILE;                                  \
        _Pragma("unroll")                                                                     \
        for (int k = 0; k < 2; k++) {                                                         \
            int idx = tid + k * 256;                                                          \
            int row = idx >> 2, c16 = idx & 3;                                                \
            const uint32_t *srch, *srcl;                                                      \
            if (cc < 24) {                                                                    \
                int li = row * 6 + (cc >> 2);                                                 \
                srch = (const uint32_t*)(size_t)s_ph[li] + (cc & 3) * 16;                     \
                srcl = (const uint32_t*)(size_t)s_pl[li] + (cc & 3) * 16;                     \
            } else {                                                                          \
                int grow = m0 + row; if (grow >= (NLIM)) grow = (NLIM) - 1;                   \
                size_t sgb = (size_t)grow * 64 + (cc - 24) * 16;                              \
                srch = (ROOTH) + sgb; srcl = (ROOTL) + sgb;                                   \
            }                                                                                 \
            uint32_t so = (uint32_t)(row * 80 + c16 * 16);                                    \
            cpa16(sb0 + 0 * PTILE + so, srch + c16 * 4);                                      \
            cpa16(sb0 + 1 * PTILE + so, srcl + c16 * 4);                                      \
            int growb = m0 + row; if (growb >= (NLIM)) growb = (NLIM) - 1;                    \
            (void)growb;                                                                      \
            const uint32_t* bh = (BTH) + (size_t)row * 448 + cc * 16;                         \
            const uint32_t* bl = (BTL) + (size_t)row * 448 + cc * 16;                         \
            cpa16(sb0 + 2 * PTILE + so, bh + c16 * 4);                                        \
            cpa16(sb0 + 3 * PTILE + so, bl + c16 * 4);                                        \
        }                                                                                     \
        CP_COMMIT();                                                                          \
    } while (0)

#define PRELOAD_PTRS(PTRH, PTRL, NLIM)                                                        \
    do {                                                                                      \
        for (int i = tid; i < 768; i += 256) {                                                \
            int row = i / 6, r = i - row * 6;                                                 \
            int grow = m0 + row; if (grow >= (NLIM)) grow = (NLIM) - 1;                       \
            s_ph[i] = (PTRH)[grow * 6 + r];                                                   \
            s_pl[i] = (PTRL)[grow * 6 + r];                                                   \
        }                                                                                     \
        __syncthreads();                                                                      \
    } while (0)

#define MMA_CHUNK(s_)                                                                         \
    do {                                                                                      \
        uint32_t sb0 = sbase + (uint32_t)((s_) * 4) * PTILE;                                  \
        _Pragma("unroll")                                                                     \
        for (int kk = 0; kk < 2; kk++) {                                                      \
            uint32_t ah[2][4], al[2][4], bh[4][4], bl[4][4];                                  \
            _Pragma("unroll")                                                                 \
            for (int mt = 0; mt < 2; mt++) {                                                  \
                uint32_t off = (uint32_t)((wm * 32 + mt * 16 + lrow) * 80 + kk * 32 + lk * 16); \
                ldm4(ah[mt], sb0 + 0 * PTILE + off);                                          \
                ldm4(al[mt], sb0 + 1 * PTILE + off);                                          \
            }                                                                                 \
            _Pragma("unroll")                                                                 \
            for (int nt = 0; nt < 4; nt++) {                                                  \
                uint32_t off = (uint32_t)((wn * 64 + nt * 16 + lrow) * 80 + kk * 32 + lk * 16); \
                ldm4(bh[nt], sb0 + 2 * PTILE + off);                                          \
                ldm4(bl[nt], sb0 + 3 * PTILE + off);                                          \
            }                                                                                 \
            _Pragma("unroll")                                                                 \
            for (int mt = 0; mt < 2; mt++)                                                    \
                _Pragma("unroll")                                                             \
                for (int nt = 0; nt < 4; nt++) {                                              \
                    mma_bf16(acc[mt][2 * nt],     ah[mt], bh[nt][0], bh[nt][2]);              \
                    mma_bf16(acc[mt][2 * nt + 1], ah[mt], bh[nt][1], bh[nt][3]);              \
                    mma_bf16(acc[mt][2 * nt],     al[mt], bh[nt][0], bh[nt][2]);              \
                    mma_bf16(acc[mt][2 * nt + 1], al[mt], bh[nt][1], bh[nt][3]);              \
                    mma_bf16(acc[mt][2 * nt],     ah[mt], bl[nt][0], bl[nt][2]);              \
                    mma_bf16(acc[mt][2 * nt + 1], ah[mt], bl[nt][1], bl[nt][3]);              \
                }                                                                             \
        }                                                                                     \
    } while (0)

// GEMM1: x1 = relu([agg1 | emb] @ B1' + bias1); split X1 written for ALL rows
__global__ __launch_bounds__(256, 2) void k_gemm1_p(const float* __restrict__ bias1, int row_base) {
    extern __shared__ char sm[];
    __shared__ unsigned long long s_ph[768], s_pl[768];
    const uint32_t sbase = smem_u32(sm);
    const int tid = threadIdx.x, lane = tid & 31, wid = tid >> 5;
    const int wm = wid & 3, wn = wid >> 2;
    const int lrow = lane & 15, lk = lane >> 4;
    const int m0 = row_base + blockIdx.x * 128;

    float acc[2][8][4];
    #pragma unroll
    for (int i = 0; i < 2; i++)
        #pragma unroll
        for (int j = 0; j < 8; j++)
            #pragma unroll
            for (int c = 0; c < 4; c++) acc[i][j][c] = 0.f;

    PRELOAD_PTRS(g_p1h, g_p1l, N_NODES);

    STAGE_CHUNK(0, 0, g_Eh, g_El, g_BT1h, g_BT1l, N_NODES);
    for (int c = 0; c < 28; c++) {
        int s = c & 1;
        if (c < 27) {
            STAGE_CHUNK(c + 1, s ^ 1, g_Eh, g_El, g_BT1h, g_BT1l, N_NODES);
            CP_WAIT(1);
        } else {
            CP_WAIT(0);
        }
        __syncthreads();
        MMA_CHUNK(s);
        __syncthreads();
    }

    const int g = lane >> 2, tc = lane & 3;
    #pragma unroll
    for (int mt = 0; mt < 2; mt++) {
        #pragma unroll
        for (int nb = 0; nb < 8; nb++) {
            int col = wn * 64 + nb * 8 + tc * 2;
            float b0 = bias1[col], b1 = bias1[col + 1];
            int pi = col >> 1;
            int r0 = m0 + wm * 32 + mt * 16 + g;
            if (r0 < N_NODES) {
                float2 v = make_float2(fmaxf(acc[mt][nb][0] + b0, 0.f), fmaxf(acc[mt][nb][1] + b1, 0.f));
                *(float2*)(g_x1 + (size_t)r0 * DIM + col) = v;
                g_X1h[(size_t)r0 * 64 + pi] = split_pack_hi(v);
                g_X1l[(size_t)r0 * 64 + pi] = split_pack_lo(v);
            }
            int r1 = r0 + 8;
            if (r1 < N_NODES) {
                float2 v = make_float2(fmaxf(acc[mt][nb][2] + b0, 0.f), fmaxf(acc[mt][nb][3] + b1, 0.f));
                *(float2*)(g_x1 + (size_t)r1 * DIM + col) = v;
                g_X1h[(size_t)r1 * 64 + pi] = split_pack_hi(v);
                g_X1l[(size_t)r1 * 64 + pi] = split_pack_lo(v);
            }
        }
    }
}

// GEMM2: x2 = [agg2 | x1] @ B2' + bias2
__global__ __launch_bounds__(256, 2) void k_gemm2_p(const float* __restrict__ bias2, int row_base) {
    extern __shared__ char sm[];
    __shared__ unsigned long long s_ph[768], s_pl[768];
    const uint32_t sbase = smem_u32(sm);
    const int tid = threadIdx.x, lane = tid & 31, wid = tid >> 5;
    const int wm = wid & 3, wn = wid >> 2;
    const int lrow = lane & 15, lk = lane >> 4;
    const int m0 = row_base + blockIdx.x * 128;

    float acc[2][8][4];
    #pragma unroll
    for (int i = 0; i < 2; i++)
        #pragma unroll
        for (int j = 0; j < 8; j++)
            #pragma unroll
            for (int c = 0; c < 4; c++) acc[i][j][c] = 0.f;

    PRELOAD_PTRS(g_p2h, g_p2l, NOUT2);

    STAGE_CHUNK(0, 0, g_X1h, g_X1l, g_BT2h, g_BT2l, NOUT2);
    for (int c = 0; c < 28; c++) {
        int s = c & 1;
        if (c < 27) {
            STAGE_CHUNK(c + 1, s ^ 1, g_X1h, g_X1l, g_BT2h, g_BT2l, NOUT2);
            CP_WAIT(1);
        } else {
            CP_WAIT(0);
        }
        __syncthreads();
        MMA_CHUNK(s);
        __syncthreads();
    }

    const int g = lane >> 2, tc = lane & 3;
    #pragma unroll
    for (int mt = 0; mt < 2; mt++) {
        #pragma unroll
        for (int nb = 0; nb < 8; nb++) {
            int col = wn * 64 + nb * 8 + tc * 2;
            float b0 = bias2[col], b1 = bias2[col + 1];
            int r0 = m0 + wm * 32 + mt * 16 + g;
            if (r0 < NOUT2)
                *(float2*)(g_x2 + (size_t)r0 * DIM + col) =
                    make_float2(acc[mt][nb][0] + b0, acc[mt][nb][1] + b1);
            int r1 = r0 + 8;
            if (r1 < NOUT2)
                *(float2*)(g_x2 + (size_t)r1 * DIM + col) =
                    make_float2(acc[mt][nb][2] + b0, acc[mt][nb][3] + b1);
        }
    }
}

// ---------------- scorer (HMMA): K=64 chunks, 2 CTAs/SM ----------------
__global__ __launch_bounds__(256, 2) void k_scorer_mma(const int* __restrict__ h_idx, const int* __restrict__ p_idx,
                                                       const float* __restrict__ sb1, const float* __restrict__ sw2,
                                                       const float* __restrict__ sb2, float* __restrict__ out) {
    extern __shared__ char sm[];
    __shared__ int sh_h[128], sh_p[128];
    uint32_t* Ah = (uint32_t*)sm;
    uint32_t* Al = (uint32_t*)(sm + STILE);
    const uint32_t sAh = smem_u32(sm), sAl = sAh + STILE, sBh = sAh + 2 * STILE, sBl = sAh + 3 * STILE;
    const int tid = threadIdx.x, lane = tid & 31, wid = tid >> 5;
    const int wm = wid & 3, wn = wid >> 2;
    const int lrow = lane & 15, lk = lane >> 4;
    const int pair0 = blockIdx.x * 128;

    for (int i = tid; i < 128; i += 256) {
        int pr = pair0 + i; if (pr >= NP) pr = NP - 1;
        sh_h[i] = h_idx[pr];
        sh_p[i] = N_HERB + p_idx[pr];
    }
    __syncthreads();

    float acc[2][8][4];
    #pragma unroll
    for (int i = 0; i < 2; i++)
        #pragma unroll
        for (int j = 0; j < 8; j++)
            #pragma unroll
            for (int c = 0; c < 4; c++) acc[i][j][c] = 0.f;

    for (int c = 0; c < 8; c++) {
        for (int i = tid; i < 1024; i += 256) {
            int row = i >> 3, c16 = i & 7;
            uint32_t so = (uint32_t)(row * 144 + c16 * 16);
            cpa16(sBh + so, g_SW1h + (size_t)row * 256 + c * 32 + c16 * 4);
            cpa16(sBl + so, g_SW1l + (size_t)row * 256 + c * 32 + c16 * 4);
        }
        CP_COMMIT();
        for (int i = tid; i < 128 * 32; i += 256) {
            int row = i >> 5, k2 = i & 31;
            int pi = ((c & 1) << 5) + k2;
            const float2* hr = (const float2*)(g_x2 + (size_t)sh_h[row] * DIM);
            const float2* pr = (const float2*)(g_x2 + (size_t)sh_p[row] * DIM);
            float2 f;
            if (c < 2)      f = hr[pi];
            else if (c < 4) f = pr[pi];
            else if (c < 6) { float2 h = hr[pi], p = pr[pi]; f = make_float2(h.x * p.x, h.y * p.y); }
            else            { float2 h = hr[pi], p = pr[pi]; f = make_float2(fabsf(h.x - p.x), fabsf(h.y - p.y)); }
            Ah[row * SSTR + k2] = split_pack_hi(f);
            Al[row * SSTR + k2] = split_pack_lo(f);
        }
        CP_WAIT(0);
        __syncthreads();
        #pragma unroll
        for (int kk = 0; kk < 4; kk++) {
            uint32_t ah[2][4], al[2][4], bh[4][4], bl[4][4];
            #pragma unroll
            for (int mt = 0; mt < 2; mt++) {
                uint32_t off = (uint32_t)((wm * 32 + mt * 16 + lrow) * 144 + kk * 32 + lk * 16);
                ldm4(ah[mt], sAh + off);
                ldm4(al[mt], sAl + off);
            }
            #pragma unroll
            for (int nt = 0; nt < 4; nt++) {
                uint32_t off = (uint32_t)((wn * 64 + nt * 16 + lrow) * 144 + kk * 32 + lk * 16);
                ldm4(bh[nt], sBh + off);
                ldm4(bl[nt], sBl + off);
            }
            #pragma unroll
            for (int mt = 0; mt < 2; mt++)
                #pragma unroll
                for (int nt = 0; nt < 4; nt++) {
                    mma_bf16(acc[mt][2 * nt],     ah[mt], bh[nt][0], bh[nt][2]);
                    mma_bf16(acc[mt][2 * nt + 1], ah[mt], bh[nt][1], bh[nt][3]);
                    mma_bf16(acc[mt][2 * nt],     al[mt], bh[nt][0], bh[nt][2]);
                    mma_bf16(acc[mt][2 * nt + 1], al[mt], bh[nt][1], bh[nt][3]);
                    mma_bf16(acc[mt][2 * nt],     ah[mt], bl[nt][0], bl[nt][2]);
                    mma_bf16(acc[mt][2 * nt + 1], ah[mt], bl[nt][1], bl[nt][3]);
                }
        }
        __syncthreads();
    }

    __syncthreads();
    float* s_part = (float*)sm;
    const int g = lane >> 2, tc = lane & 3;
    #pragma unroll
    for (int mt = 0; mt < 2; mt++) {
        float s0 = 0.f, s1 = 0.f;
        #pragma unroll
        for (int nb = 0; nb < 8; nb++) {
            int col = wn * 64 + nb * 8 + tc * 2;
            float w0 = sw2[col], w1 = sw2[col + 1];
            float bb0 = sb1[col], bb1 = sb1[col + 1];
            s0 += fmaxf(acc[mt][nb][0] + bb0, 0.f) * w0 + fmaxf(acc[mt][nb][1] + bb1, 0.f) * w1;
            s1 += fmaxf(acc[mt][nb][2] + bb0, 0.f) * w0 + fmaxf(acc[mt][nb][3] + bb1, 0.f) * w1;
        }
        s0 += __shfl_xor_sync(0xffffffff, s0, 1); s0 += __shfl_xor_sync(0xffffffff, s0, 2);
        s1 += __shfl_xor_sync(0xffffffff, s1, 1); s1 += __shfl_xor_sync(0xffffffff, s1, 2);
        if (tc == 0) {
            int r0 = wm * 32 + mt * 16 + g;
            s_part[r0 * 2 + wn] = s0;
            s_part[(r0 + 8) * 2 + wn] = s1;
        }
    }
    __syncthreads();
    if (tid < 128) {
        int pr = pair0 + tid;
        if (pr < NP) out[pr] = s_part[tid * 2] + s_part[tid * 2 + 1] + sb2[0];
    }
}

// ---------------- launch ----------------
extern "C" void kernel_launch(void* const* d_in, const int* in_sizes, int n_in,
                              void* d_out, int out_size) {
    const int*   edge_index = (const int*)d_in[0];
    const int*   edge_type  = (const int*)d_in[1];
    const int*   h_idx      = (const int*)d_in[2];
    const int*   p_idx      = (const int*)d_in[3];
    const float* node_emb   = (const float*)d_in[4];
    const float* basis1 = (const float*)d_in[5];
    const float* comp1  = (const float*)d_in[6];
    const float* root1  = (const float*)d_in[7];
    const float* bias1  = (const float*)d_in[8];
    const float* basis2 = (const float*)d_in[9];
    const float* comp2  = (const float*)d_in[10];
    const float* root2  = (const float*)d_in[11];
    const float* bias2  = (const float*)d_in[12];
    const float* sw1 = (const float*)d_in[13];
    const float* sb1 = (const float*)d_in[14];
    const float* sw2 = (const float*)d_in[15];
    const float* sb2 = (const float*)d_in[16];
    float* out = (float*)d_out;

    cudaFuncSetAttribute(k_gemm1_p, cudaFuncAttributeMaxDynamicSharedMemorySize, PSMEM);
    cudaFuncSetAttribute(k_gemm2_p, cudaFuncAttributeMaxDynamicSharedMemorySize, PSMEM);
    cudaFuncSetAttribute(k_scorer_mma, cudaFuncAttributeMaxDynamicSharedMemorySize, SSMEM);

    static cudaStream_t s1 = nullptr;
    static cudaEvent_t evFork = nullptr, evG1A = nullptr, evM1A = nullptr,
                       evG2A = nullptr, evM2A = nullptr, evBuild = nullptr;
    if (s1 == nullptr) {
        cudaStreamCreateWithFlags(&s1, cudaStreamNonBlocking);
        cudaEventCreateWithFlags(&evFork, cudaEventDisableTiming);
        cudaEventCreateWithFlags(&evBuild, cudaEventDisableTiming);
        cudaEventCreateWithFlags(&evG1A, cudaEventDisableTiming);
        cudaEventCreateWithFlags(&evM1A, cudaEventDisableTiming);
        cudaEventCreateWithFlags(&evG2A, cudaEventDisableTiming);
        cudaEventCreateWithFlags(&evM2A, cudaEventDisableTiming);
    }

    // fork: builds on s1
    cudaEventRecord(evFork, 0);
    cudaStreamWaitEvent(s1, evFork, 0);
    k_build_all<<<(BLD_EMB + 255) / 256, 256, 0, s1>>>(basis1, comp1, root1,
                                                       basis2, comp2, root2,
                                                       sw1, node_emb);
    cudaEventRecord(evBuild, s1);

    // main: CSR
    int* cnt_ptr = nullptr;
    cudaGetSymbolAddress((void**)&cnt_ptr, g_cnt);
    cudaMemsetAsync(cnt_ptr, 0, NSEG1 * sizeof(int), 0);
    k_count<<<(NE + 255) / 256, 256>>>(edge_index, edge_type);
    k_scan_a<<<NBLK, SCAN_BLK>>>();
    k_scan_c<<<NBLK, SCAN_BLK>>>();
    k_fill<<<(NE + 255) / 256, 256>>>(edge_index, edge_type);

    // gather1a on main; gemm1a (s1) overlaps gather1b (main)
    k_gather1<<<(S1A * 32 + 255) / 256, 256>>>(node_emb, 0, S1A);
    cudaEventRecord(evG1A, 0);

    cudaStreamWaitEvent(s1, evG1A, 0);      // s1: build done (in-order) + g1a pointers/data ready
    k_gemm1_p<<<G1_BLKA, 256, PSMEM, s1>>>(bias1, 0);
    cudaEventRecord(evM1A, s1);

    k_gather1<<<((NSEG1 - S1A) * 32 + 255) / 256, 256>>>(node_emb, S1A, NSEG1 - S1A);
    cudaStreamWaitEvent(0, evBuild, 0);
    k_gemm1_p<<<G1_BLKB, 256, PSMEM>>>(bias1, R1SPLIT);
    cudaStreamWaitEvent(0, evM1A, 0);       // x1/X1 fully written

    // gather2a on main; gemm2a (s1) overlaps gather2b (main)
    k_gather2<<<(S2A * 32 + 255) / 256, 256>>>(0, S2A);
    cudaEventRecord(evG2A, 0);

    cudaStreamWaitEvent(s1, evG2A, 0);
    k_gemm2_p<<<G2_BLKA, 256, PSMEM, s1>>>(bias2, 0);
    cudaEventRecord(evM2A, s1);

    k_gather2<<<((NSEG2 - S2A) * 32 + 255) / 256, 256>>>(S2A, NSEG2 - S2A);
    k_gemm2_p<<<G2_BLKB, 256, PSMEM>>>(bias2, R2SPLIT);
    cudaStreamWaitEvent(0, evM2A, 0);       // x2 fully written

    k_scorer_mma<<<(NP + 127) / 128, 256, SSMEM>>>(h_idx, p_idx, sb1, sw2, sb2, out);
}

// round 16
// speedup vs baseline: 1.0562x; 1.0477x over previous
#include <cuda_runtime.h>
#include <cuda_bf16.h>
#include <cstdint>

#define N_NODES 60000
#define N_HERB  5000
#define NOUT2   25000
#define DIM     128
#define NREL    6
#define NB      30
#define NE      600000
#define NP      40000
#define NSEG1   (N_NODES * NREL)   // 360000
#define NSEG2   (NOUT2 * NREL)     // 150000
#define SCAN_BLK 1024
#define NBLK    ((NSEG1 + SCAN_BLK - 1) / SCAN_BLK)   // 352

// phase-split points (row-aligned to 128-row GEMM blocks)
#define G1_BLKA 235
#define R1SPLIT (G1_BLKA * 128)        // 30080
#define G1_BLKB 234
#define S1A     (R1SPLIT * NREL)       // 180480
#define G2_BLKA 98
#define R2SPLIT (G2_BLKA * 128)        // 12544
#define G2_BLKB 98
#define S2A     (R2SPLIT * NREL)       // 75264

// ---------------- scratch ----------------
__device__ uint32_t g_A1h[(size_t)NSEG1 * 64], g_A1l[(size_t)NSEG1 * 64];
__device__ uint32_t g_A2h[(size_t)NSEG2 * 64], g_A2l[(size_t)NSEG2 * 64];
__device__ uint32_t g_Eh[(size_t)N_NODES * 64], g_El[(size_t)N_NODES * 64];
__device__ uint32_t g_X1h[(size_t)NOUT2 * 64], g_X1l[(size_t)NOUT2 * 64];
__device__ float g_x1[(size_t)N_NODES * DIM];
__device__ float g_x2[(size_t)NOUT2 * DIM];
__device__ int   g_cnt[NSEG1];
__device__ int   g_off[NSEG1 + 1];
__device__ int   g_cursor[NSEG1];
__device__ int   g_esrc[NE];
__device__ int   g_bsum[NBLK];
__device__ uint32_t g_BT1h[128 * 448], g_BT1l[128 * 448];
__device__ uint32_t g_BT2h[128 * 448], g_BT2l[128 * 448];
__device__ uint32_t g_SW1h[128 * 256], g_SW1l[128 * 256];

// ---------------- helpers ----------------
__device__ __forceinline__ uint32_t smem_u32(const void* p) {
    uint32_t a;
    asm("{ .reg .u64 t; cvta.to.shared.u64 t, %1; cvt.u32.u64 %0, t; }" : "=r"(a) : "l"(p));
    return a;
}
__device__ __forceinline__ void ldm4(uint32_t* r, uint32_t addr) {
    asm volatile("ldmatrix.sync.aligned.m8n8.x4.shared.b16 {%0,%1,%2,%3}, [%4];"
        : "=r"(r[0]), "=r"(r[1]), "=r"(r[2]), "=r"(r[3]) : "r"(addr));
}
__device__ __forceinline__ void mma_bf16(float* d, const uint32_t* a, uint32_t b0, uint32_t b1) {
    asm volatile("mma.sync.aligned.m16n8k16.row.col.f32.bf16.bf16.f32 "
        "{%0,%1,%2,%3}, {%4,%5,%6,%7}, {%8,%9}, {%0,%1,%2,%3};"
        : "+f"(d[0]), "+f"(d[1]), "+f"(d[2]), "+f"(d[3])
        : "r"(a[0]), "r"(a[1]), "r"(a[2]), "r"(a[3]), "r"(b0), "r"(b1));
}
__device__ __forceinline__ uint32_t split_pack_hi(float2 f) {
    __nv_bfloat162 h;
    h.x = __float2bfloat16_rn(f.x); h.y = __float2bfloat16_rn(f.y);
    return *(uint32_t*)&h;
}
__device__ __forceinline__ uint32_t split_pack_lo(float2 f) {
    __nv_bfloat16 hx = __float2bfloat16_rn(f.x), hy = __float2bfloat16_rn(f.y);
    __nv_bfloat162 l;
    l.x = __float2bfloat16_rn(f.x - __bfloat162float(hx));
    l.y = __float2bfloat16_rn(f.y - __bfloat162float(hy));
    return *(uint32_t*)&l;
}
__device__ __forceinline__ void cpa16(uint32_t saddr, const void* g) {
    asm volatile("cp.async.cg.shared.global [%0], [%1], 16;" :: "r"(saddr), "l"(g));
}
#define CP_COMMIT() asm volatile("cp.async.commit_group;" ::: "memory")
#define CP_WAIT(n)  asm volatile("cp.async.wait_group %0;" :: "n"(n) : "memory")

#define PSTR 20
#define PTILE (128 * PSTR * 4)    // 10240 B
#define PSMEM (8 * PTILE)         // 81920 B -> 2 CTAs/SM
#define SSTR 36
#define STILE (128 * SSTR * 4)    // 18432 B
#define SSMEM (4 * STILE)         // 73728 B -> 2 CTAs/SM

// ---------------- merged weight/emb build ----------------
#define BLD_W1   (128 * 448)
#define BLD_W2   (BLD_W1 + 128 * 448)
#define BLD_SW   (BLD_W2 + 128 * 256)
#define BLD_EMB  (BLD_SW + N_NODES * 32)
__global__ void k_build_all(const float* __restrict__ basis1, const float* __restrict__ comp1,
                            const float* __restrict__ root1,
                            const float* __restrict__ basis2, const float* __restrict__ comp2,
                            const float* __restrict__ root2,
                            const float* __restrict__ sw1, const float* __restrict__ X) {
    int gid = blockIdx.x * blockDim.x + threadIdx.x;
    if (gid >= BLD_EMB) return;
    if (gid < BLD_W2) {
        const float* basis = (gid < BLD_W1) ? basis1 : basis2;
        const float* comp  = (gid < BLD_W1) ? comp1 : comp2;
        const float* root  = (gid < BLD_W1) ? root1 : root2;
        uint32_t* dh = (gid < BLD_W1) ? g_BT1h : g_BT2h;
        uint32_t* dl = (gid < BLD_W1) ? g_BT1l : g_BT2l;
        int idx = (gid < BLD_W1) ? gid : gid - BLD_W1;
        int o = idx / 448, j = idx % 448, k0 = j * 2;
        float w0, w1;
        if (k0 < 768) {
            int r = k0 >> 7, d0 = k0 & 127;
            w0 = 0.f; w1 = 0.f;
            #pragma unroll
            for (int b = 0; b < NB; b++) {
                float cc = comp[r * NB + b];
                w0 += cc * basis[b * 16384 + d0 * 128 + o];
                w1 += cc * basis[b * 16384 + (d0 + 1) * 128 + o];
            }
        } else {
            int d0 = k0 - 768;
            w0 = root[d0 * 128 + o]; w1 = root[(d0 + 1) * 128 + o];
        }
        float2 f = make_float2(w0, w1);
        dh[idx] = split_pack_hi(f);
        dl[idx] = split_pack_lo(f);
    } else if (gid < BLD_SW) {
        int idx = gid - BLD_W2;
        int o = idx >> 8, j = idx & 255, k0 = j * 2;
        float2 f = make_float2(sw1[k0 * 128 + o], sw1[(k0 + 1) * 128 + o]);
        g_SW1h[idx] = split_pack_hi(f);
        g_SW1l[idx] = split_pack_lo(f);
    } else {
        int idx = gid - BLD_SW;
        float4 f = ((const float4*)X)[idx];
        float2 f01 = make_float2(f.x, f.y), f23 = make_float2(f.z, f.w);
        *(uint2*)(g_Eh + (size_t)idx * 2) = make_uint2(split_pack_hi(f01), split_pack_hi(f23));
        *(uint2*)(g_El + (size_t)idx * 2) = make_uint2(split_pack_lo(f01), split_pack_lo(f23));
    }
}

// ---------------- CSR build ----------------
__global__ void k_count(const int* __restrict__ ei, const int* __restrict__ et) {
    int e = blockIdx.x * blockDim.x + threadIdx.x;
    if (e < NE) atomicAdd(&g_cnt[ei[NE + e] * NREL + et[e]], 1);
}
__global__ __launch_bounds__(SCAN_BLK) void k_scan_a() {
    __shared__ int sm[SCAN_BLK];
    int t = threadIdx.x;
    int gid = blockIdx.x * SCAN_BLK + t;
    int v = (gid < NSEG1) ? g_cnt[gid] : 0;
    sm[t] = v;
    __syncthreads();
    for (int d = 1; d < SCAN_BLK; d <<= 1) {
        int x = (t >= d) ? sm[t - d] : 0;
        __syncthreads();
        sm[t] += x;
        __syncthreads();
    }
    if (gid < NSEG1) g_off[gid] = sm[t] - v;
    if (t == SCAN_BLK - 1) g_bsum[blockIdx.x] = sm[t];
}
__global__ __launch_bounds__(SCAN_BLK) void k_scan_c() {
    __shared__ int red[SCAN_BLK];
    int t = threadIdx.x;
    red[t] = (t < (int)blockIdx.x && t < NBLK) ? g_bsum[t] : 0;
    __syncthreads();
    for (int d = SCAN_BLK / 2; d > 0; d >>= 1) {
        if (t < d) red[t] += red[t + d];
        __syncthreads();
    }
    int pre = red[0];
    int gid = blockIdx.x * SCAN_BLK + t;
    if (gid < NSEG1) {
        int o = g_off[gid] + pre;
        g_off[gid] = o;
        g_cursor[gid] = o;
    }
    if (gid == 0) g_off[NSEG1] = NE;
}
__global__ void k_fill(const int* __restrict__ ei, const int* __restrict__ et) {
    int e = blockIdx.x * blockDim.x + threadIdx.x;
    if (e < NE) {
        int seg = ei[NE + e] * NREL + et[e];
        int pos = atomicAdd(&g_cursor[seg], 1);
        g_esrc[pos] = ei[e];
    }
}

// ---------------- gathers (seg-range parameterized) ----------------
__global__ __launch_bounds__(256) void k_gather1(const float* __restrict__ X, int seg0, int nseg) {
    int w = (int)((blockIdx.x * 256u + threadIdx.x) >> 5);
    if (w >= nseg) return;
    w += seg0;
    int lane = threadIdx.x & 31;
    int s0 = g_off[w], s1 = g_off[w + 1];
    float4 acc = make_float4(0.f, 0.f, 0.f, 0.f);
    for (int e = s0; e < s1; e++) {
        const float4 v = *(const float4*)(X + (size_t)g_esrc[e] * DIM + lane * 4);
        acc.x += v.x; acc.y += v.y; acc.z += v.z; acc.w += v.w;
    }
    float sc = (s1 > s0) ? 1.f / (float)(s1 - s0) : 0.f;
    float2 f01 = make_float2(acc.x * sc, acc.y * sc);
    float2 f23 = make_float2(acc.z * sc, acc.w * sc);
    size_t base = (size_t)w * 64 + lane * 2;
    *(uint2*)(g_A1h + base) = make_uint2(split_pack_hi(f01), split_pack_hi(f23));
    *(uint2*)(g_A1l + base) = make_uint2(split_pack_lo(f01), split_pack_lo(f23));
}
__global__ __launch_bounds__(256) void k_gather2(int seg0, int nseg) {
    int w = (int)((blockIdx.x * 256u + threadIdx.x) >> 5);
    if (w >= nseg) return;
    w += seg0;
    int lane = threadIdx.x & 31;
    int s0 = g_off[w], s1 = g_off[w + 1];
    float4 acc = make_float4(0.f, 0.f, 0.f, 0.f);
    for (int e = s0; e < s1; e++) {
        const float4 v = *(const float4*)(g_x1 + (size_t)g_esrc[e] * DIM + lane * 4);
        acc.x += v.x; acc.y += v.y; acc.z += v.z; acc.w += v.w;
    }
    float sc = (s1 > s0) ? 1.f / (float)(s1 - s0) : 0.f;
    float2 f01 = make_float2(acc.x * sc, acc.y * sc);
    float2 f23 = make_float2(acc.z * sc, acc.w * sc);
    size_t base = (size_t)w * 64 + lane * 2;
    *(uint2*)(g_A2h + base) = make_uint2(split_pack_hi(f01), split_pack_hi(f23));
    *(uint2*)(g_A2l + base) = make_uint2(split_pack_lo(f01), split_pack_lo(f23));
}

// ---------------- pipelined HMMA GEMM core ----------------
#define STAGE_CHUNK(c_, s_, AGGH, AGGL, ROOTH, ROOTL, BTH, BTL, NLIM)                         \
    do {                                                                                      \
        int cc = (c_);                                                                        \
        uint32_t sb0 = sbase + (uint32_t)((s_) * 4) * PTILE;                                  \
        _Pragma("unroll")                                                                     \
        for (int k = 0; k < 2; k++) {                                                         \
            int idx = tid + k * 256;                                                          \
            int row = idx >> 2, c16 = idx & 3;                                                \
            int grow = m0 + row; if (grow >= (NLIM)) grow = (NLIM) - 1;                       \
            const uint32_t *srch, *srcl;                                                      \
            if (cc < 24) {                                                                    \
                size_t sgb = ((size_t)grow * 6 + (cc >> 2)) * 64 + (cc & 3) * 16;             \
                srch = (AGGH) + sgb; srcl = (AGGL) + sgb;                                     \
            } else {                                                                          \
                size_t sgb = (size_t)grow * 64 + (cc - 24) * 16;                              \
                srch = (ROOTH) + sgb; srcl = (ROOTL) + sgb;                                   \
            }                                                                                 \
            uint32_t so = (uint32_t)(row * 80 + c16 * 16);                                    \
            cpa16(sb0 + 0 * PTILE + so, srch + c16 * 4);                                      \
            cpa16(sb0 + 1 * PTILE + so, srcl + c16 * 4);                                      \
            const uint32_t* bh = (BTH) + (size_t)row * 448 + cc * 16;                         \
            const uint32_t* bl = (BTL) + (size_t)row * 448 + cc * 16;                         \
            cpa16(sb0 + 2 * PTILE + so, bh + c16 * 4);                                        \
            cpa16(sb0 + 3 * PTILE + so, bl + c16 * 4);                                        \
        }                                                                                     \
        CP_COMMIT();                                                                          \
    } while (0)

#define MMA_CHUNK(s_)                                                                         \
    do {                                                                                      \
        uint32_t sb0 = sbase + (uint32_t)((s_) * 4) * PTILE;                                  \
        _Pragma("unroll")                                                                     \
        for (int kk = 0; kk < 2; kk++) {                                                      \
            uint32_t ah[2][4], al[2][4], bh[4][4], bl[4][4];                                  \
            _Pragma("unroll")                                                                 \
            for (int mt = 0; mt < 2; mt++) {                                                  \
                uint32_t off = (uint32_t)((wm * 32 + mt * 16 + lrow) * 80 + kk * 32 + lk * 16); \
                ldm4(ah[mt], sb0 + 0 * PTILE + off);                                          \
                ldm4(al[mt], sb0 + 1 * PTILE + off);                                          \
            }                                                                                 \
            _Pragma("unroll")                                                                 \
            for (int nt = 0; nt < 4; nt++) {                                                  \
                uint32_t off = (uint32_t)((wn * 64 + nt * 16 + lrow) * 80 + kk * 32 + lk * 16); \
                ldm4(bh[nt], sb0 + 2 * PTILE + off);                                          \
                ldm4(bl[nt], sb0 + 3 * PTILE + off);                                          \
            }                                                                                 \
            _Pragma("unroll")                                                                 \
            for (int mt = 0; mt < 2; mt++)                                                    \
                _Pragma("unroll")                                                             \
                for (int nt = 0; nt < 4; nt++) {                                              \
                    mma_bf16(acc[mt][2 * nt],     ah[mt], bh[nt][0], bh[nt][2]);              \
                    mma_bf16(acc[mt][2 * nt + 1], ah[mt], bh[nt][1], bh[nt][3]);              \
                    mma_bf16(acc[mt][2 * nt],     al[mt], bh[nt][0], bh[nt][2]);              \
                    mma_bf16(acc[mt][2 * nt + 1], al[mt], bh[nt][1], bh[nt][3]);              \
                    mma_bf16(acc[mt][2 * nt],     ah[mt], bl[nt][0], bl[nt][2]);              \
                    mma_bf16(acc[mt][2 * nt + 1], ah[mt], bl[nt][1], bl[nt][3]);              \
                }                                                                             \
        }                                                                                     \
    } while (0)

// GEMM1 (row_base parameterized)
__global__ __launch_bounds__(256, 2) void k_gemm1_p(const float* __restrict__ bias1, int row_base) {
    extern __shared__ char sm[];
    const uint32_t sbase = smem_u32(sm);
    const int tid = threadIdx.x, lane = tid & 31, wid = tid >> 5;
    const int wm = wid & 3, wn = wid >> 2;
    const int lrow = lane & 15, lk = lane >> 4;
    const int m0 = row_base + blockIdx.x * 128;

    float acc[2][8][4];
    #pragma unroll
    for (int i = 0; i < 2; i++)
        #pragma unroll
        for (int j = 0; j < 8; j++)
            #pragma unroll
            for (int c = 0; c < 4; c++) acc[i][j][c] = 0.f;

    STAGE_CHUNK(0, 0, g_A1h, g_A1l, g_Eh, g_El, g_BT1h, g_BT1l, N_NODES);
    for (int c = 0; c < 28; c++) {
        int s = c & 1;
        if (c < 27) {
            STAGE_CHUNK(c + 1, s ^ 1, g_A1h, g_A1l, g_Eh, g_El, g_BT1h, g_BT1l, N_NODES);
            CP_WAIT(1);
        } else {
            CP_WAIT(0);
        }
        __syncthreads();
        MMA_CHUNK(s);
        __syncthreads();
    }

    const int g = lane >> 2, tc = lane & 3;
    #pragma unroll
    for (int mt = 0; mt < 2; mt++) {
        #pragma unroll
        for (int nb = 0; nb < 8; nb++) {
            int col = wn * 64 + nb * 8 + tc * 2;
            float b0 = bias1[col], b1 = bias1[col + 1];
            int pi = col >> 1;
            int r0 = m0 + wm * 32 + mt * 16 + g;
            if (r0 < N_NODES) {
                float2 v = make_float2(fmaxf(acc[mt][nb][0] + b0, 0.f), fmaxf(acc[mt][nb][1] + b1, 0.f));
                *(float2*)(g_x1 + (size_t)r0 * DIM + col) = v;
                if (r0 < NOUT2) {
                    g_X1h[(size_t)r0 * 64 + pi] = split_pack_hi(v);
                    g_X1l[(size_t)r0 * 64 + pi] = split_pack_lo(v);
                }
            }
            int r1 = r0 + 8;
            if (r1 < N_NODES) {
                float2 v = make_float2(fmaxf(acc[mt][nb][2] + b0, 0.f), fmaxf(acc[mt][nb][3] + b1, 0.f));
                *(float2*)(g_x1 + (size_t)r1 * DIM + col) = v;
                if (r1 < NOUT2) {
                    g_X1h[(size_t)r1 * 64 + pi] = split_pack_hi(v);
                    g_X1l[(size_t)r1 * 64 + pi] = split_pack_lo(v);
                }
            }
        }
    }
}

// GEMM2 (row_base parameterized)
__global__ __launch_bounds__(256, 2) void k_gemm2_p(const float* __restrict__ bias2, int row_base) {
    extern __shared__ char sm[];
    const uint32_t sbase = smem_u32(sm);
    const int tid = threadIdx.x, lane = tid & 31, wid = tid >> 5;
    const int wm = wid & 3, wn = wid >> 2;
    const int lrow = lane & 15, lk = lane >> 4;
    const int m0 = row_base + blockIdx.x * 128;

    float acc[2][8][4];
    #pragma unroll
    for (int i = 0; i < 2; i++)
        #pragma unroll
        for (int j = 0; j < 8; j++)
            #pragma unroll
            for (int c = 0; c < 4; c++) acc[i][j][c] = 0.f;

    STAGE_CHUNK(0, 0, g_A2h, g_A2l, g_X1h, g_X1l, g_BT2h, g_BT2l, NOUT2);
    for (int c = 0; c < 28; c++) {
        int s = c & 1;
        if (c < 27) {
            STAGE_CHUNK(c + 1, s ^ 1, g_A2h, g_A2l, g_X1h, g_X1l, g_BT2h, g_BT2l, NOUT2);
            CP_WAIT(1);
        } else {
            CP_WAIT(0);
        }
        __syncthreads();
        MMA_CHUNK(s);
        __syncthreads();
    }

    const int g = lane >> 2, tc = lane & 3;
    #pragma unroll
    for (int mt = 0; mt < 2; mt++) {
        #pragma unroll
        for (int nb = 0; nb < 8; nb++) {
            int col = wn * 64 + nb * 8 + tc * 2;
            float b0 = bias2[col], b1 = bias2[col + 1];
            int r0 = m0 + wm * 32 + mt * 16 + g;
            if (r0 < NOUT2)
                *(float2*)(g_x2 + (size_t)r0 * DIM + col) =
                    make_float2(acc[mt][nb][0] + b0, acc[mt][nb][1] + b1);
            int r1 = r0 + 8;
            if (r1 < NOUT2)
                *(float2*)(g_x2 + (size_t)r1 * DIM + col) =
                    make_float2(acc[mt][nb][2] + b0, acc[mt][nb][3] + b1);
        }
    }
}

// ---------------- scorer (HMMA): K=64 chunks, 2 CTAs/SM ----------------
__global__ __launch_bounds__(256, 2) void k_scorer_mma(const int* __restrict__ h_idx, const int* __restrict__ p_idx,
                                                       const float* __restrict__ sb1, const float* __restrict__ sw2,
                                                       const float* __restrict__ sb2, float* __restrict__ out) {
    extern __shared__ char sm[];
    __shared__ int sh_h[128], sh_p[128];
    uint32_t* Ah = (uint32_t*)sm;
    uint32_t* Al = (uint32_t*)(sm + STILE);
    const uint32_t sAh = smem_u32(sm), sAl = sAh + STILE, sBh = sAh + 2 * STILE, sBl = sAh + 3 * STILE;
    const int tid = threadIdx.x, lane = tid & 31, wid = tid >> 5;
    const int wm = wid & 3, wn = wid >> 2;
    const int lrow = lane & 15, lk = lane >> 4;
    const int pair0 = blockIdx.x * 128;

    for (int i = tid; i < 128; i += 256) {
        int pr = pair0 + i; if (pr >= NP) pr = NP - 1;
        sh_h[i] = h_idx[pr];
        sh_p[i] = N_HERB + p_idx[pr];
    }
    __syncthreads();

    float acc[2][8][4];
    #pragma unroll
    for (int i = 0; i < 2; i++)
        #pragma unroll
        for (int j = 0; j < 8; j++)
            #pragma unroll
            for (int c = 0; c < 4; c++) acc[i][j][c] = 0.f;

    for (int c = 0; c < 8; c++) {
        for (int i = tid; i < 1024; i += 256) {
            int row = i >> 3, c16 = i & 7;
            uint32_t so = (uint32_t)(row * 144 + c16 * 16);
            cpa16(sBh + so, g_SW1h + (size_t)row * 256 + c * 32 + c16 * 4);
            cpa16(sBl + so, g_SW1l + (size_t)row * 256 + c * 32 + c16 * 4);
        }
        CP_COMMIT();
        for (int i = tid; i < 128 * 32; i += 256) {
            int row = i >> 5, k2 = i & 31;
            int pi = ((c & 1) << 5) + k2;
            const float2* hr = (const float2*)(g_x2 + (size_t)sh_h[row] * DIM);
            const float2* pr = (const float2*)(g_x2 + (size_t)sh_p[row] * DIM);
            float2 f;
            if (c < 2)      f = hr[pi];
            else if (c < 4) f = pr[pi];
            else if (c < 6) { float2 h = hr[pi], p = pr[pi]; f = make_float2(h.x * p.x, h.y * p.y); }
            else            { float2 h = hr[pi], p = pr[pi]; f = make_float2(fabsf(h.x - p.x), fabsf(h.y - p.y)); }
            Ah[row * SSTR + k2] = split_pack_hi(f);
            Al[row * SSTR + k2] = split_pack_lo(f);
        }
        CP_WAIT(0);
        __syncthreads();
        #pragma unroll
        for (int kk = 0; kk < 4; kk++) {
            uint32_t ah[2][4], al[2][4], bh[4][4], bl[4][4];
            #pragma unroll
            for (int mt = 0; mt < 2; mt++) {
                uint32_t off = (uint32_t)((wm * 32 + mt * 16 + lrow) * 144 + kk * 32 + lk * 16);
                ldm4(ah[mt], sAh + off);
                ldm4(al[mt], sAl + off);
            }
            #pragma unroll
            for (int nt = 0; nt < 4; nt++) {
                uint32_t off = (uint32_t)((wn * 64 + nt * 16 + lrow) * 144 + kk * 32 + lk * 16);
                ldm4(bh[nt], sBh + off);
                ldm4(bl[nt], sBl + off);
            }
            #pragma unroll
            for (int mt = 0; mt < 2; mt++)
                #pragma unroll
                for (int nt = 0; nt < 4; nt++) {
                    mma_bf16(acc[mt][2 * nt],     ah[mt], bh[nt][0], bh[nt][2]);
                    mma_bf16(acc[mt][2 * nt + 1], ah[mt], bh[nt][1], bh[nt][3]);
                    mma_bf16(acc[mt][2 * nt],     al[mt], bh[nt][0], bh[nt][2]);
                    mma_bf16(acc[mt][2 * nt + 1], al[mt], bh[nt][1], bh[nt][3]);
                    mma_bf16(acc[mt][2 * nt],     ah[mt], bl[nt][0], bl[nt][2]);
                    mma_bf16(acc[mt][2 * nt + 1], ah[mt], bl[nt][1], bl[nt][3]);
                }
        }
        __syncthreads();
    }

    __syncthreads();
    float* s_part = (float*)sm;
    const int g = lane >> 2, tc = lane & 3;
    #pragma unroll
    for (int mt = 0; mt < 2; mt++) {
        float s0 = 0.f, s1 = 0.f;
        #pragma unroll
        for (int nb = 0; nb < 8; nb++) {
            int col = wn * 64 + nb * 8 + tc * 2;
            float w0 = sw2[col], w1 = sw2[col + 1];
            float bb0 = sb1[col], bb1 = sb1[col + 1];
            s0 += fmaxf(acc[mt][nb][0] + bb0, 0.f) * w0 + fmaxf(acc[mt][nb][1] + bb1, 0.f) * w1;
            s1 += fmaxf(acc[mt][nb][2] + bb0, 0.f) * w0 + fmaxf(acc[mt][nb][3] + bb1, 0.f) * w1;
        }
        s0 += __shfl_xor_sync(0xffffffff, s0, 1); s0 += __shfl_xor_sync(0xffffffff, s0, 2);
        s1 += __shfl_xor_sync(0xffffffff, s1, 1); s1 += __shfl_xor_sync(0xffffffff, s1, 2);
        if (tc == 0) {
            int r0 = wm * 32 + mt * 16 + g;
            s_part[r0 * 2 + wn] = s0;
            s_part[(r0 + 8) * 2 + wn] = s1;
        }
    }
    __syncthreads();
    if (tid < 128) {
        int pr = pair0 + tid;
        if (pr < NP) out[pr] = s_part[tid * 2] + s_part[tid * 2 + 1] + sb2[0];
    }
}

// ---------------- launch ----------------
extern "C" void kernel_launch(void* const* d_in, const int* in_sizes, int n_in,
                              void* d_out, int out_size) {
    const int*   edge_index = (const int*)d_in[0];
    const int*   edge_type  = (const int*)d_in[1];
    const int*   h_idx      = (const int*)d_in[2];
    const int*   p_idx      = (const int*)d_in[3];
    const float* node_emb   = (const float*)d_in[4];
    const float* basis1 = (const float*)d_in[5];
    const float* comp1  = (const float*)d_in[6];
    const float* root1  = (const float*)d_in[7];
    const float* bias1  = (const float*)d_in[8];
    const float* basis2 = (const float*)d_in[9];
    const float* comp2  = (const float*)d_in[10];
    const float* root2  = (const float*)d_in[11];
    const float* bias2  = (const float*)d_in[12];
    const float* sw1 = (const float*)d_in[13];
    const float* sb1 = (const float*)d_in[14];
    const float* sw2 = (const float*)d_in[15];
    const float* sb2 = (const float*)d_in[16];
    float* out = (float*)d_out;

    cudaFuncSetAttribute(k_gemm1_p, cudaFuncAttributeMaxDynamicSharedMemorySize, PSMEM);
    cudaFuncSetAttribute(k_gemm2_p, cudaFuncAttributeMaxDynamicSharedMemorySize, PSMEM);
    cudaFuncSetAttribute(k_scorer_mma, cudaFuncAttributeMaxDynamicSharedMemorySize, SSMEM);

    static cudaStream_t s1 = nullptr;
    static cudaEvent_t evFork = nullptr, evG1A = nullptr, evM1A = nullptr,
                       evG2A = nullptr, evM2A = nullptr, evBuild = nullptr;
    if (s1 == nullptr) {
        cudaStreamCreateWithFlags(&s1, cudaStreamNonBlocking);
        cudaEventCreateWithFlags(&evFork, cudaEventDisableTiming);
        cudaEventCreateWithFlags(&evBuild, cudaEventDisableTiming);
        cudaEventCreateWithFlags(&evG1A, cudaEventDisableTiming);
        cudaEventCreateWithFlags(&evM1A, cudaEventDisableTiming);
        cudaEventCreateWithFlags(&evG2A, cudaEventDisableTiming);
        cudaEventCreateWithFlags(&evM2A, cudaEventDisableTiming);
    }

    // fork: builds on s1
    cudaEventRecord(evFork, 0);
    cudaStreamWaitEvent(s1, evFork, 0);
    k_build_all<<<(BLD_EMB + 255) / 256, 256, 0, s1>>>(basis1, comp1, root1,
                                                       basis2, comp2, root2,
                                                       sw1, node_emb);
    cudaEventRecord(evBuild, s1);

    // main: CSR
    int* cnt_ptr = nullptr;
    cudaGetSymbolAddress((void**)&cnt_ptr, g_cnt);
    cudaMemsetAsync(cnt_ptr, 0, NSEG1 * sizeof(int), 0);
    k_count<<<(NE + 255) / 256, 256>>>(edge_index, edge_type);
    k_scan_a<<<NBLK, SCAN_BLK>>>();
    k_scan_c<<<NBLK, SCAN_BLK>>>();
    k_fill<<<(NE + 255) / 256, 256>>>(edge_index, edge_type);

    // gather1a on main; gemm1a (s1) overlaps gather1b (main)
    k_gather1<<<(S1A * 32 + 255) / 256, 256>>>(node_emb, 0, S1A);
    cudaEventRecord(evG1A, 0);

    cudaStreamWaitEvent(s1, evG1A, 0);                       // s1: build done (in-order) + g1a
    k_gemm1_p<<<G1_BLKA, 256, PSMEM, s1>>>(bias1, 0);
    cudaEventRecord(evM1A, s1);

    k_gather1<<<((NSEG1 - S1A) * 32 + 255) / 256, 256>>>(node_emb, S1A, NSEG1 - S1A);
    cudaStreamWaitEvent(0, evBuild, 0);
    k_gemm1_p<<<G1_BLKB, 256, PSMEM>>>(bias1, R1SPLIT);
    cudaStreamWaitEvent(0, evM1A, 0);                        // x1 fully written

    // gather2a on main; gemm2a (s1) overlaps gather2b (main)
    k_gather2<<<(S2A * 32 + 255) / 256, 256>>>(0, S2A);
    cudaEventRecord(evG2A, 0);

    cudaStreamWaitEvent(s1, evG2A, 0);
    k_gemm2_p<<<G2_BLKA, 256, PSMEM, s1>>>(bias2, 0);
    cudaEventRecord(evM2A, s1);

    k_gather2<<<((NSEG2 - S2A) * 32 + 255) / 256, 256>>>(S2A, NSEG2 - S2A);
    k_gemm2_p<<<G2_BLKB, 256, PSMEM>>>(bias2, R2SPLIT);
    cudaStreamWaitEvent(0, evM2A, 0);                        // x2 fully written

    k_scorer_mma<<<(NP + 127) / 128, 256, SSMEM>>>(h_idx, p_idx, sb1, sw2, sb2, out);
}

// round 17
// speedup vs baseline: 1.5561x; 1.4733x over previous
#include <cuda_runtime.h>
#include <cuda_bf16.h>
#include <cstdint>

#define N_NODES 60000
#define N_HERB  5000
#define NOUT2   25000
#define DIM     128
#define NREL    6
#define NB      30
#define NE      600000
#define NP      40000
#define NSEG1   (N_NODES * NREL)   // 360000
#define NSEG2   (NOUT2 * NREL)     // 150000
#define SCAN_BLK 1024
#define NBLK    ((NSEG1 + SCAN_BLK - 1) / SCAN_BLK)   // 352

// phase-split points (row-aligned to 128-row GEMM blocks)
#define G1_BLKA 235
#define R1SPLIT (G1_BLKA * 128)        // 30080
#define G1_BLKB 234
#define S1A     (R1SPLIT * NREL)       // 180480
#define G2_BLKA 98
#define R2SPLIT (G2_BLKA * 128)        // 12544
#define G2_BLKB 98
#define S2A     (R2SPLIT * NREL)       // 75264

// ---------------- scratch ----------------
__device__ uint32_t g_A1h[(size_t)NSEG1 * 64], g_A1l[(size_t)NSEG1 * 64];
__device__ uint32_t g_A2h[(size_t)NSEG2 * 64], g_A2l[(size_t)NSEG2 * 64];
__device__ uint32_t g_Eh[(size_t)N_NODES * 64], g_El[(size_t)N_NODES * 64];
__device__ uint32_t g_X1h[(size_t)NOUT2 * 64], g_X1l[(size_t)NOUT2 * 64];
__device__ float g_x1[(size_t)N_NODES * DIM];
__device__ float g_x2[(size_t)NOUT2 * DIM];
__device__ int   g_cnt[NSEG1];
__device__ int   g_off[NSEG1 + 1];
__device__ int   g_cursor[NSEG1];
__device__ int   g_esrc[NE];
__device__ int   g_bsum[NBLK];
__device__ uint32_t g_BT1h[128 * 448], g_BT1l[128 * 448];
__device__ uint32_t g_BT2h[128 * 448], g_BT2l[128 * 448];
__device__ uint32_t g_SW1h[128 * 256], g_SW1l[128 * 256];

// ---------------- helpers ----------------
__device__ __forceinline__ uint32_t smem_u32(const void* p) {
    uint32_t a;
    asm("{ .reg .u64 t; cvta.to.shared.u64 t, %1; cvt.u32.u64 %0, t; }" : "=r"(a) : "l"(p));
    return a;
}
__device__ __forceinline__ void ldm4(uint32_t* r, uint32_t addr) {
    asm volatile("ldmatrix.sync.aligned.m8n8.x4.shared.b16 {%0,%1,%2,%3}, [%4];"
        : "=r"(r[0]), "=r"(r[1]), "=r"(r[2]), "=r"(r[3]) : "r"(addr));
}
__device__ __forceinline__ void mma_bf16(float* d, const uint32_t* a, uint32_t b0, uint32_t b1) {
    asm volatile("mma.sync.aligned.m16n8k16.row.col.f32.bf16.bf16.f32 "
        "{%0,%1,%2,%3}, {%4,%5,%6,%7}, {%8,%9}, {%0,%1,%2,%3};"
        : "+f"(d[0]), "+f"(d[1]), "+f"(d[2]), "+f"(d[3])
        : "r"(a[0]), "r"(a[1]), "r"(a[2]), "r"(a[3]), "r"(b0), "r"(b1));
}
__device__ __forceinline__ uint32_t split_pack_hi(float2 f) {
    __nv_bfloat162 h;
    h.x = __float2bfloat16_rn(f.x); h.y = __float2bfloat16_rn(f.y);
    return *(uint32_t*)&h;
}
__device__ __forceinline__ uint32_t split_pack_lo(float2 f) {
    __nv_bfloat16 hx = __float2bfloat16_rn(f.x), hy = __float2bfloat16_rn(f.y);
    __nv_bfloat162 l;
    l.x = __float2bfloat16_rn(f.x - __bfloat162float(hx));
    l.y = __float2bfloat16_rn(f.y - __bfloat162float(hy));
    return *(uint32_t*)&l;
}
__device__ __forceinline__ void cpa16(uint32_t saddr, const void* g) {
    asm volatile("cp.async.cg.shared.global [%0], [%1], 16;" :: "r"(saddr), "l"(g));
}
#define CP_COMMIT() asm volatile("cp.async.commit_group;" ::: "memory")
#define CP_WAIT(n)  asm volatile("cp.async.wait_group %0;" :: "n"(n) : "memory")

#define PSTR 20
#define PTILE (128 * PSTR * 4)    // 10240 B
#define PSMEM (8 * PTILE)         // 81920 B -> 2 CTAs/SM
#define SSTR 36
#define STILE (128 * SSTR * 4)    // 18432 B
#define SSMEM (4 * STILE)         // 73728 B -> 2 CTAs/SM

// ---------------- merged weight/emb build ----------------
#define BLD_W1   (128 * 448)
#define BLD_W2   (BLD_W1 + 128 * 448)
#define BLD_SW   (BLD_W2 + 128 * 256)
#define BLD_EMB  (BLD_SW + N_NODES * 32)
__global__ void k_build_all(const float* __restrict__ basis1, const float* __restrict__ comp1,
                            const float* __restrict__ root1,
                            const float* __restrict__ basis2, const float* __restrict__ comp2,
                            const float* __restrict__ root2,
                            const float* __restrict__ sw1, const float* __restrict__ X) {
    int gid = blockIdx.x * blockDim.x + threadIdx.x;
    if (gid >= BLD_EMB) return;
    if (gid < BLD_W2) {
        const float* basis = (gid < BLD_W1) ? basis1 : basis2;
        const float* comp  = (gid < BLD_W1) ? comp1 : comp2;
        const float* root  = (gid < BLD_W1) ? root1 : root2;
        uint32_t* dh = (gid < BLD_W1) ? g_BT1h : g_BT2h;
        uint32_t* dl = (gid < BLD_W1) ? g_BT1l : g_BT2l;
        int idx = (gid < BLD_W1) ? gid : gid - BLD_W1;
        int o = idx / 448, j = idx % 448, k0 = j * 2;
        float w0, w1;
        if (k0 < 768) {
            int r = k0 >> 7, d0 = k0 & 127;
            w0 = 0.f; w1 = 0.f;
            #pragma unroll
            for (int b = 0; b < NB; b++) {
                float cc = comp[r * NB + b];
                w0 += cc * basis[b * 16384 + d0 * 128 + o];
                w1 += cc * basis[b * 16384 + (d0 + 1) * 128 + o];
            }
        } else {
            int d0 = k0 - 768;
            w0 = root[d0 * 128 + o]; w1 = root[(d0 + 1) * 128 + o];
        }
        float2 f = make_float2(w0, w1);
        dh[idx] = split_pack_hi(f);
        dl[idx] = split_pack_lo(f);
    } else if (gid < BLD_SW) {
        int idx = gid - BLD_W2;
        int o = idx >> 8, j = idx & 255, k0 = j * 2;
        float2 f = make_float2(sw1[k0 * 128 + o], sw1[(k0 + 1) * 128 + o]);
        g_SW1h[idx] = split_pack_hi(f);
        g_SW1l[idx] = split_pack_lo(f);
    } else {
        int idx = gid - BLD_SW;
        float4 f = ((const float4*)X)[idx];
        float2 f01 = make_float2(f.x, f.y), f23 = make_float2(f.z, f.w);
        *(uint2*)(g_Eh + (size_t)idx * 2) = make_uint2(split_pack_hi(f01), split_pack_hi(f23));
        *(uint2*)(g_El + (size_t)idx * 2) = make_uint2(split_pack_lo(f01), split_pack_lo(f23));
    }
}

// ---------------- CSR build ----------------
__global__ void k_count(const int* __restrict__ ei, const int* __restrict__ et) {
    int e = blockIdx.x * blockDim.x + threadIdx.x;
    if (e < NE) atomicAdd(&g_cnt[ei[NE + e] * NREL + et[e]], 1);
}
__global__ __launch_bounds__(SCAN_BLK) void k_scan_a() {
    __shared__ int sm[SCAN_BLK];
    int t = threadIdx.x;
    int gid = blockIdx.x * SCAN_BLK + t;
    int v = (gid < NSEG1) ? g_cnt[gid] : 0;
    sm[t] = v;
    __syncthreads();
    for (int d = 1; d < SCAN_BLK; d <<= 1) {
        int x = (t >= d) ? sm[t - d] : 0;
        __syncthreads();
        sm[t] += x;
        __syncthreads();
    }
    if (gid < NSEG1) g_off[gid] = sm[t] - v;
    if (t == SCAN_BLK - 1) g_bsum[blockIdx.x] = sm[t];
}
__global__ __launch_bounds__(SCAN_BLK) void k_scan_c() {
    __shared__ int red[SCAN_BLK];
    int t = threadIdx.x;
    red[t] = (t < (int)blockIdx.x && t < NBLK) ? g_bsum[t] : 0;
    __syncthreads();
    for (int d = SCAN_BLK / 2; d > 0; d >>= 1) {
        if (t < d) red[t] += red[t + d];
        __syncthreads();
    }
    int pre = red[0];
    int gid = blockIdx.x * SCAN_BLK + t;
    if (gid < NSEG1) {
        int o = g_off[gid] + pre;
        g_off[gid] = o;
        g_cursor[gid] = o;
    }
    if (gid == 0) g_off[NSEG1] = NE;
}
__global__ void k_fill(const int* __restrict__ ei, const int* __restrict__ et) {
    int e = blockIdx.x * blockDim.x + threadIdx.x;
    if (e < NE) {
        int seg = ei[NE + e] * NREL + et[e];
        int pos = atomicAdd(&g_cursor[seg], 1);
        g_esrc[pos] = ei[e];
    }
}

// ---------------- gathers (seg-range parameterized) ----------------
__global__ __launch_bounds__(256) void k_gather1(const float* __restrict__ X, int seg0, int nseg) {
    int w = (int)((blockIdx.x * 256u + threadIdx.x) >> 5);
    if (w >= nseg) return;
    w += seg0;
    int lane = threadIdx.x & 31;
    int s0 = g_off[w], s1 = g_off[w + 1];
    float4 acc = make_float4(0.f, 0.f, 0.f, 0.f);
    for (int e = s0; e < s1; e++) {
        const float4 v = *(const float4*)(X + (size_t)g_esrc[e] * DIM + lane * 4);
        acc.x += v.x; acc.y += v.y; acc.z += v.z; acc.w += v.w;
    }
    float sc = (s1 > s0) ? 1.f / (float)(s1 - s0) : 0.f;
    float2 f01 = make_float2(acc.x * sc, acc.y * sc);
    float2 f23 = make_float2(acc.z * sc, acc.w * sc);
    size_t base = (size_t)w * 64 + lane * 2;
    *(uint2*)(g_A1h + base) = make_uint2(split_pack_hi(f01), split_pack_hi(f23));
    *(uint2*)(g_A1l + base) = make_uint2(split_pack_lo(f01), split_pack_lo(f23));
}
__global__ __launch_bounds__(256) void k_gather2(int seg0, int nseg) {
    int w = (int)((blockIdx.x * 256u + threadIdx.x) >> 5);
    if (w >= nseg) return;
    w += seg0;
    int lane = threadIdx.x & 31;
    int s0 = g_off[w], s1 = g_off[w + 1];
    float4 acc = make_float4(0.f, 0.f, 0.f, 0.f);
    for (int e = s0; e < s1; e++) {
        const float4 v = *(const float4*)(g_x1 + (size_t)g_esrc[e] * DIM + lane * 4);
        acc.x += v.x; acc.y += v.y; acc.z += v.z; acc.w += v.w;
    }
    float sc = (s1 > s0) ? 1.f / (float)(s1 - s0) : 0.f;
    float2 f01 = make_float2(acc.x * sc, acc.y * sc);
    float2 f23 = make_float2(acc.z * sc, acc.w * sc);
    size_t base = (size_t)w * 64 + lane * 2;
    *(uint2*)(g_A2h + base) = make_uint2(split_pack_hi(f01), split_pack_hi(f23));
    *(uint2*)(g_A2l + base) = make_uint2(split_pack_lo(f01), split_pack_lo(f23));
}

// ---------------- pipelined HMMA GEMM core ----------------
#define STAGE_CHUNK(c_, s_, AGGH, AGGL, ROOTH, ROOTL, BTH, BTL, NLIM)                         \
    do {                                                                                      \
        int cc = (c_);                                                                        \
        uint32_t sb0 = sbase + (uint32_t)((s_) * 4) * PTILE;                                  \
        _Pragma("unroll")                                                                     \
        for (int k = 0; k < 2; k++) {                                                         \
            int idx = tid + k * 256;                                                          \
            int row = idx >> 2, c16 = idx & 3;                                                \
            int grow = m0 + row; if (grow >= (NLIM)) grow = (NLIM) - 1;                       \
            const uint32_t *srch, *srcl;                                                      \
            if (cc < 24) {                                                                    \
                size_t sgb = ((size_t)grow * 6 + (cc >> 2)) * 64 + (cc & 3) * 16;             \
                srch = (AGGH) + sgb; srcl = (AGGL) + sgb;                                     \
            } else {                                                                          \
                size_t sgb = (size_t)grow * 64 + (cc - 24) * 16;                              \
                srch = (ROOTH) + sgb; srcl = (ROOTL) + sgb;                                   \
            }                                                                                 \
            uint32_t so = (uint32_t)(row * 80 + c16 * 16);                                    \
            cpa16(sb0 + 0 * PTILE + so, srch + c16 * 4);                                      \
            cpa16(sb0 + 1 * PTILE + so, srcl + c16 * 4);                                      \
            const uint32_t* bh = (BTH) + (size_t)row * 448 + cc * 16;                         \
            const uint32_t* bl = (BTL) + (size_t)row * 448 + cc * 16;                         \
            cpa16(sb0 + 2 * PTILE + so, bh + c16 * 4);                                        \
            cpa16(sb0 + 3 * PTILE + so, bl + c16 * 4);                                        \
        }                                                                                     \
        CP_COMMIT();                                                                          \
    } while (0)

#define MMA_CHUNK(s_)                                                                         \
    do {                                                                                      \
        uint32_t sb0 = sbase + (uint32_t)((s_) * 4) * PTILE;                                  \
        _Pragma("unroll")                                                                     \
        for (int kk = 0; kk < 2; kk++) {                                                      \
            uint32_t ah[2][4], al[2][4], bh[4][4], bl[4][4];                                  \
            _Pragma("unroll")                                                                 \
            for (int mt = 0; mt < 2; mt++) {                                                  \
                uint32_t off = (uint32_t)((wm * 32 + mt * 16 + lrow) * 80 + kk * 32 + lk * 16); \
                ldm4(ah[mt], sb0 + 0 * PTILE + off);                                          \
                ldm4(al[mt], sb0 + 1 * PTILE + off);                                          \
            }                                                                                 \
            _Pragma("unroll")                                                                 \
            for (int nt = 0; nt < 4; nt++) {                                                  \
                uint32_t off = (uint32_t)((wn * 64 + nt * 16 + lrow) * 80 + kk * 32 + lk * 16); \
                ldm4(bh[nt], sb0 + 2 * PTILE + off);                                          \
                ldm4(bl[nt], sb0 + 3 * PTILE + off);                                          \
            }                                                                                 \
            _Pragma("unroll")                                                                 \
            for (int mt = 0; mt < 2; mt++)                                                    \
                _Pragma("unroll")                                                             \
                for (int nt = 0; nt < 4; nt++) {                                              \
                    mma_bf16(acc[mt][2 * nt],     ah[mt], bh[nt][0], bh[nt][2]);              \
                    mma_bf16(acc[mt][2 * nt + 1], ah[mt], bh[nt][1], bh[nt][3]);              \
                    mma_bf16(acc[mt][2 * nt],     al[mt], bh[nt][0], bh[nt][2]);              \
                    mma_bf16(acc[mt][2 * nt + 1], al[mt], bh[nt][1], bh[nt][3]);              \
                    mma_bf16(acc[mt][2 * nt],     ah[mt], bl[nt][0], bl[nt][2]);              \
                    mma_bf16(acc[mt][2 * nt + 1], ah[mt], bl[nt][1], bl[nt][3]);              \
                }                                                                             \
        }                                                                                     \
    } while (0)

// GEMM1 (row_base parameterized)
__global__ __launch_bounds__(256, 2) void k_gemm1_p(const float* __restrict__ bias1, int row_base) {
    extern __shared__ char sm[];
    const uint32_t sbase = smem_u32(sm);
    const int tid = threadIdx.x, lane = tid & 31, wid = tid >> 5;
    const int wm = wid & 3, wn = wid >> 2;
    const int lrow = lane & 15, lk = lane >> 4;
    const int m0 = row_base + blockIdx.x * 128;

    float acc[2][8][4];
    #pragma unroll
    for (int i = 0; i < 2; i++)
        #pragma unroll
        for (int j = 0; j < 8; j++)
            #pragma unroll
            for (int c = 0; c < 4; c++) acc[i][j][c] = 0.f;

    STAGE_CHUNK(0, 0, g_A1h, g_A1l, g_Eh, g_El, g_BT1h, g_BT1l, N_NODES);
    for (int c = 0; c < 28; c++) {
        int s = c & 1;
        if (c < 27) {
            STAGE_CHUNK(c + 1, s ^ 1, g_A1h, g_A1l, g_Eh, g_El, g_BT1h, g_BT1l, N_NODES);
            CP_WAIT(1);
        } else {
            CP_WAIT(0);
        }
        __syncthreads();
        MMA_CHUNK(s);
        __syncthreads();
    }

    const int g = lane >> 2, tc = lane & 3;
    #pragma unroll
    for (int mt = 0; mt < 2; mt++) {
        #pragma unroll
        for (int nb = 0; nb < 8; nb++) {
            int col = wn * 64 + nb * 8 + tc * 2;
            float b0 = bias1[col], b1 = bias1[col + 1];
            int pi = col >> 1;
            int r0 = m0 + wm * 32 + mt * 16 + g;
            if (r0 < N_NODES) {
                float2 v = make_float2(fmaxf(acc[mt][nb][0] + b0, 0.f), fmaxf(acc[mt][nb][1] + b1, 0.f));
                *(float2*)(g_x1 + (size_t)r0 * DIM + col) = v;
                if (r0 < NOUT2) {
                    g_X1h[(size_t)r0 * 64 + pi] = split_pack_hi(v);
                    g_X1l[(size_t)r0 * 64 + pi] = split_pack_lo(v);
                }
            }
            int r1 = r0 + 8;
            if (r1 < N_NODES) {
                float2 v = make_float2(fmaxf(acc[mt][nb][2] + b0, 0.f), fmaxf(acc[mt][nb][3] + b1, 0.f));
                *(float2*)(g_x1 + (size_t)r1 * DIM + col) = v;
                if (r1 < NOUT2) {
                    g_X1h[(size_t)r1 * 64 + pi] = split_pack_hi(v);
                    g_X1l[(size_t)r1 * 64 + pi] = split_pack_lo(v);
                }
            }
        }
    }
}

// GEMM2 (row_base parameterized)
__global__ __launch_bounds__(256, 2) void k_gemm2_p(const float* __restrict__ bias2, int row_base) {
    extern __shared__ char sm[];
    const uint32_t sbase = smem_u32(sm);
    const int tid = threadIdx.x, lane = tid & 31, wid = tid >> 5;
    const int wm = wid & 3, wn = wid >> 2;
    const int lrow = lane & 15, lk = lane >> 4;
    const int m0 = row_base + blockIdx.x * 128;

    float acc[2][8][4];
    #pragma unroll
    for (int i = 0; i < 2; i++)
        #pragma unroll
        for (int j = 0; j < 8; j++)
            #pragma unroll
            for (int c = 0; c < 4; c++) acc[i][j][c] = 0.f;

    STAGE_CHUNK(0, 0, g_A2h, g_A2l, g_X1h, g_X1l, g_BT2h, g_BT2l, NOUT2);
    for (int c = 0; c < 28; c++) {
        int s = c & 1;
        if (c < 27) {
            STAGE_CHUNK(c + 1, s ^ 1, g_A2h, g_A2l, g_X1h, g_X1l, g_BT2h, g_BT2l, NOUT2);
            CP_WAIT(1);
        } else {
            CP_WAIT(0);
        }
        __syncthreads();
        MMA_CHUNK(s);
        __syncthreads();
    }

    const int g = lane >> 2, tc = lane & 3;
    #pragma unroll
    for (int mt = 0; mt < 2; mt++) {
        #pragma unroll
        for (int nb = 0; nb < 8; nb++) {
            int col = wn * 64 + nb * 8 + tc * 2;
            float b0 = bias2[col], b1 = bias2[col + 1];
            int r0 = m0 + wm * 32 + mt * 16 + g;
            if (r0 < NOUT2)
                *(float2*)(g_x2 + (size_t)r0 * DIM + col) =
                    make_float2(acc[mt][nb][0] + b0, acc[mt][nb][1] + b1);
            int r1 = r0 + 8;
            if (r1 < NOUT2)
                *(float2*)(g_x2 + (size_t)r1 * DIM + col) =
                    make_float2(acc[mt][nb][2] + b0, acc[mt][nb][3] + b1);
        }
    }
}

// ---------------- scorer (HMMA): K=64 chunks, 2 CTAs/SM ----------------
__global__ __launch_bounds__(256, 2) void k_scorer_mma(const int* __restrict__ h_idx, const int* __restrict__ p_idx,
                                                       const float* __restrict__ sb1, const float* __restrict__ sw2,
                                                       const float* __restrict__ sb2, float* __restrict__ out) {
    extern __shared__ char sm[];
    __shared__ int sh_h[128], sh_p[128];
    uint32_t* Ah = (uint32_t*)sm;
    uint32_t* Al = (uint32_t*)(sm + STILE);
    const uint32_t sAh = smem_u32(sm), sAl = sAh + STILE, sBh = sAh + 2 * STILE, sBl = sAh + 3 * STILE;
    const int tid = threadIdx.x, lane = tid & 31, wid = tid >> 5;
    const int wm = wid & 3, wn = wid >> 2;
    const int lrow = lane & 15, lk = lane >> 4;
    const int pair0 = blockIdx.x * 128;

    for (int i = tid; i < 128; i += 256) {
        int pr = pair0 + i; if (pr >= NP) pr = NP - 1;
        sh_h[i] = h_idx[pr];
        sh_p[i] = N_HERB + p_idx[pr];
    }
    __syncthreads();

    float acc[2][8][4];
    #pragma unroll
    for (int i = 0; i < 2; i++)
        #pragma unroll
        for (int j = 0; j < 8; j++)
            #pragma unroll
            for (int c = 0; c < 4; c++) acc[i][j][c] = 0.f;

    for (int c = 0; c < 8; c++) {
        for (int i = tid; i < 1024; i += 256) {
            int row = i >> 3, c16 = i & 7;
            uint32_t so = (uint32_t)(row * 144 + c16 * 16);
            cpa16(sBh + so, g_SW1h + (size_t)row * 256 + c * 32 + c16 * 4);
            cpa16(sBl + so, g_SW1l + (size_t)row * 256 + c * 32 + c16 * 4);
        }
        CP_COMMIT();
        for (int i = tid; i < 128 * 32; i += 256) {
            int row = i >> 5, k2 = i & 31;
            int pi = ((c & 1) << 5) + k2;
            const float2* hr = (const float2*)(g_x2 + (size_t)sh_h[row] * DIM);
            const float2* pr = (const float2*)(g_x2 + (size_t)sh_p[row] * DIM);
            float2 f;
            if (c < 2)      f = hr[pi];
            else if (c < 4) f = pr[pi];
            else if (c < 6) { float2 h = hr[pi], p = pr[pi]; f = make_float2(h.x * p.x, h.y * p.y); }
            else            { float2 h = hr[pi], p = pr[pi]; f = make_float2(fabsf(h.x - p.x), fabsf(h.y - p.y)); }
            Ah[row * SSTR + k2] = split_pack_hi(f);
            Al[row * SSTR + k2] = split_pack_lo(f);
        }
        CP_WAIT(0);
        __syncthreads();
        #pragma unroll
        for (int kk = 0; kk < 4; kk++) {
            uint32_t ah[2][4], al[2][4], bh[4][4], bl[4][4];
            #pragma unroll
            for (int mt = 0; mt < 2; mt++) {
                uint32_t off = (uint32_t)((wm * 32 + mt * 16 + lrow) * 144 + kk * 32 + lk * 16);
                ldm4(ah[mt], sAh + off);
                ldm4(al[mt], sAl + off);
            }
            #pragma unroll
            for (int nt = 0; nt < 4; nt++) {
                uint32_t off = (uint32_t)((wn * 64 + nt * 16 + lrow) * 144 + kk * 32 + lk * 16);
                ldm4(bh[nt], sBh + off);
                ldm4(bl[nt], sBl + off);
            }
            #pragma unroll
            for (int mt = 0; mt < 2; mt++)
                #pragma unroll
                for (int nt = 0; nt < 4; nt++) {
                    mma_bf16(acc[mt][2 * nt],     ah[mt], bh[nt][0], bh[nt][2]);
                    mma_bf16(acc[mt][2 * nt + 1], ah[mt], bh[nt][1], bh[nt][3]);
                    mma_bf16(acc[mt][2 * nt],     al[mt], bh[nt][0], bh[nt][2]);
                    mma_bf16(acc[mt][2 * nt + 1], al[mt], bh[nt][1], bh[nt][3]);
                    mma_bf16(acc[mt][2 * nt],     ah[mt], bl[nt][0], bl[nt][2]);
                    mma_bf16(acc[mt][2 * nt + 1], ah[mt], bl[nt][1], bl[nt][3]);
                }
        }
        __syncthreads();
    }

    __syncthreads();
    float* s_part = (float*)sm;
    const int g = lane >> 2, tc = lane & 3;
    #pragma unroll
    for (int mt = 0; mt < 2; mt++) {
        float s0 = 0.f, s1 = 0.f;
        #pragma unroll
        for (int nb = 0; nb < 8; nb++) {
            int col = wn * 64 + nb * 8 + tc * 2;
            float w0 = sw2[col], w1 = sw2[col + 1];
            float bb0 = sb1[col], bb1 = sb1[col + 1];
            s0 += fmaxf(acc[mt][nb][0] + bb0, 0.f) * w0 + fmaxf(acc[mt][nb][1] + bb1, 0.f) * w1;
            s1 += fmaxf(acc[mt][nb][2] + bb0, 0.f) * w0 + fmaxf(acc[mt][nb][3] + bb1, 0.f) * w1;
        }
        s0 += __shfl_xor_sync(0xffffffff, s0, 1); s0 += __shfl_xor_sync(0xffffffff, s0, 2);
        s1 += __shfl_xor_sync(0xffffffff, s1, 1); s1 += __shfl_xor_sync(0xffffffff, s1, 2);
        if (tc == 0) {
            int r0 = wm * 32 + mt * 16 + g;
            s_part[r0 * 2 + wn] = s0;
            s_part[(r0 + 8) * 2 + wn] = s1;
        }
    }
    __syncthreads();
    if (tid < 128) {
        int pr = pair0 + tid;
        if (pr < NP) out[pr] = s_part[tid * 2] + s_part[tid * 2 + 1] + sb2[0];
    }
}

// ---------------- launch ----------------
extern "C" void kernel_launch(void* const* d_in, const int* in_sizes, int n_in,
                              void* d_out, int out_size) {
    const int*   edge_index = (const int*)d_in[0];
    const int*   edge_type  = (const int*)d_in[1];
    const int*   h_idx      = (const int*)d_in[2];
    const int*   p_idx      = (const int*)d_in[3];
    const float* node_emb   = (const float*)d_in[4];
    const float* basis1 = (const float*)d_in[5];
    const float* comp1  = (const float*)d_in[6];
    const float* root1  = (const float*)d_in[7];
    const float* bias1  = (const float*)d_in[8];
    const float* basis2 = (const float*)d_in[9];
    const float* comp2  = (const float*)d_in[10];
    const float* root2  = (const float*)d_in[11];
    const float* bias2  = (const float*)d_in[12];
    const float* sw1 = (const float*)d_in[13];
    const float* sb1 = (const float*)d_in[14];
    const float* sw2 = (const float*)d_in[15];
    const float* sb2 = (const float*)d_in[16];
    float* out = (float*)d_out;

    cudaFuncSetAttribute(k_gemm1_p, cudaFuncAttributeMaxDynamicSharedMemorySize, PSMEM);
    cudaFuncSetAttribute(k_gemm2_p, cudaFuncAttributeMaxDynamicSharedMemorySize, PSMEM);
    cudaFuncSetAttribute(k_scorer_mma, cudaFuncAttributeMaxDynamicSharedMemorySize, SSMEM);

    static cudaStream_t s1 = nullptr;
    static cudaEvent_t evFork = nullptr, evG1A = nullptr, evM1A = nullptr,
                       evG2A = nullptr, evM2A = nullptr, evBuild = nullptr;
    if (s1 == nullptr) {
        cudaStreamCreateWithFlags(&s1, cudaStreamNonBlocking);
        cudaEventCreateWithFlags(&evFork, cudaEventDisableTiming);
        cudaEventCreateWithFlags(&evBuild, cudaEventDisableTiming);
        cudaEventCreateWithFlags(&evG1A, cudaEventDisableTiming);
        cudaEventCreateWithFlags(&evM1A, cudaEventDisableTiming);
        cudaEventCreateWithFlags(&evG2A, cudaEventDisableTiming);
        cudaEventCreateWithFlags(&evM2A, cudaEventDisableTiming);
    }

    // fork: builds on s1
    cudaEventRecord(evFork, 0);
    cudaStreamWaitEvent(s1, evFork, 0);
    k_build_all<<<(BLD_EMB + 255) / 256, 256, 0, s1>>>(basis1, comp1, root1,
                                                       basis2, comp2, root2,
                                                       sw1, node_emb);
    cudaEventRecord(evBuild, s1);

    // main: CSR
    int* cnt_ptr = nullptr;
    cudaGetSymbolAddress((void**)&cnt_ptr, g_cnt);
    cudaMemsetAsync(cnt_ptr, 0, NSEG1 * sizeof(int), 0);
    k_count<<<(NE + 255) / 256, 256>>>(edge_index, edge_type);
    k_scan_a<<<NBLK, SCAN_BLK>>>();
    k_scan_c<<<NBLK, SCAN_BLK>>>();
    k_fill<<<(NE + 255) / 256, 256>>>(edge_index, edge_type);

    // gather1a on main; gemm1a (s1) overlaps gather1b (main)
    k_gather1<<<(S1A * 32 + 255) / 256, 256>>>(node_emb, 0, S1A);
    cudaEventRecord(evG1A, 0);

    cudaStreamWaitEvent(s1, evG1A, 0);                       // s1: build done (in-order) + g1a
    k_gemm1_p<<<G1_BLKA, 256, PSMEM, s1>>>(bias1, 0);
    cudaEventRecord(evM1A, s1);

    k_gather1<<<((NSEG1 - S1A) * 32 + 255) / 256, 256>>>(node_emb, S1A, NSEG1 - S1A);
    cudaStreamWaitEvent(0, evBuild, 0);
    k_gemm1_p<<<G1_BLKB, 256, PSMEM>>>(bias1, R1SPLIT);
    cudaStreamWaitEvent(0, evM1A, 0);                        // x1 fully written

    // gather2a on main; gemm2a (s1) overlaps gather2b (main)
    k_gather2<<<(S2A * 32 + 255) / 256, 256>>>(0, S2A);
    cudaEventRecord(evG2A, 0);

    cudaStreamWaitEvent(s1, evG2A, 0);
    k_gemm2_p<<<G2_BLKA, 256, PSMEM, s1>>>(bias2, 0);
    cudaEventRecord(evM2A, s1);

    k_gather2<<<((NSEG2 - S2A) * 32 + 255) / 256, 256>>>(S2A, NSEG2 - S2A);
    k_gemm2_p<<<G2_BLKB, 256, PSMEM>>>(bias2, R2SPLIT);
    cudaStreamWaitEvent(0, evM2A, 0);                        // x2 fully written

    k_scorer_mma<<<(NP + 127) / 128, 256, SSMEM>>>(h_idx, p_idx, sb1, sw2, sb2, out);
}